// round 6
// baseline (speedup 1.0000x reference)
#include <cuda_runtime.h>
#include <cuda_bf16.h>
#include <math.h>
#include <stdint.h>

#define BATCH   8
#define SEQLEN  4096
#define DIM     512
#define MROWS   (BATCH * SEQLEN)   // 32768
#define CHUNK   128
#define NCHUNK  (SEQLEN / CHUNK)   // 32

// ================= static scratch =================
__device__ float g_a  [(size_t)MROWS * DIM];
__device__ float g_b  [(size_t)MROWS * DIM];
__device__ float g_Hin[BATCH * NCHUNK * DIM];
__device__ float g_P  [BATCH * NCHUNK * DIM];
__device__ float g_Q  [BATCH * NCHUNK * DIM];

// bf16 split operands. A3 = [hs | x] : 32768 x 1024
__device__ __align__(16) __nv_bfloat16 g_A3hi[(size_t)MROWS * 1024];
__device__ __align__(16) __nv_bfloat16 g_A3lo[(size_t)MROWS * 1024];
__device__ __align__(16) __nv_bfloat16 g_W1hi[1024 * 512];   // interleaved [Wg;B]
__device__ __align__(16) __nv_bfloat16 g_W1lo[1024 * 512];
__device__ __align__(16) __nv_bfloat16 g_W3hi[512 * 1024];   // [C | D]
__device__ __align__(16) __nv_bfloat16 g_W3lo[512 * 1024];

// ================= PTX helpers (sm_80+ family-safe) ========
__device__ __forceinline__ uint32_t smem_u32(const void* p) {
    uint32_t a;
    asm("{ .reg .u64 t; cvta.to.shared.u64 t, %1; cvt.u32.u64 %0, t; }"
        : "=r"(a) : "l"(p));
    return a;
}
__device__ __forceinline__ void cp16(uint32_t s, const void* g) {
    asm volatile("cp.async.cg.shared.global [%0], [%1], 16;"
                 :: "r"(s), "l"(__cvta_generic_to_global(g)) : "memory");
}
#define CP_COMMIT() asm volatile("cp.async.commit_group;" ::: "memory")
#define CP_WAIT(n)  asm volatile("cp.async.wait_group %0;" :: "n"(n) : "memory")

#define LDSM4(r0, r1, r2, r3, addr) \
    asm volatile("ldmatrix.sync.aligned.m8n8.x4.shared.b16 {%0,%1,%2,%3}, [%4];" \
                 : "=r"(r0), "=r"(r1), "=r"(r2), "=r"(r3) : "r"(addr))

#define MMA16816(c, a, b0, b1) \
    asm volatile("mma.sync.aligned.m16n8k16.row.col.f32.bf16.bf16.f32 " \
                 "{%0,%1,%2,%3}, {%4,%5,%6,%7}, {%8,%9}, {%0,%1,%2,%3};" \
                 : "+f"((c)[0]), "+f"((c)[1]), "+f"((c)[2]), "+f"((c)[3]) \
                 : "r"((a)[0]), "r"((a)[1]), "r"((a)[2]), "r"((a)[3]), \
                   "r"(b0), "r"(b1))

// smem tile: rows x 32 bf16 (64B data), row stride 80B (ldmatrix conflict-free)
#define T_STRIDE  80
#define A_BYTES   (128 * T_STRIDE)   // 10240 (A tile: 128 rows)
#define W_BYTES   (256 * T_STRIDE)   // 20480 (W tile: 256 rows)
#define BUF_BYTES (2 * A_BYTES + 2 * W_BYTES)   // 61440
#define NSTAGE    3
#define SMEM_REQ  (NSTAGE * BUF_BYTES)          // 184320 (> epilogue needs)

// ================= bf16 split =================
__device__ __forceinline__ void bsplit(float v, __nv_bfloat16& hi, __nv_bfloat16& lo) {
    hi = __float2bfloat16_rn(v);
    lo = __float2bfloat16_rn(v - __bfloat162float(hi));
}

// =======================================================================
// conv kernels
// =======================================================================
__global__ void conv_w_kernel(const float* __restrict__ Wg, const float* __restrict__ B,
                              const float* __restrict__ C,  const float* __restrict__ D)
{
    int idx = blockIdx.x * blockDim.x + threadIdx.x;
    if (idx < 1024 * 512) {
        int r = idx >> 9, k = idx & 511, h = r >> 1;
        float v = (r & 1) ? B[h * 512 + k] : Wg[h * 512 + k];
        __nv_bfloat16 hi, lo; bsplit(v, hi, lo);
        g_W1hi[idx] = hi; g_W1lo[idx] = lo;
    } else {
        int j = idx - 1024 * 512;
        int n = j >> 10, k = j & 1023;
        float v = (k < 512) ? C[n * 512 + k] : D[n * 512 + k - 512];
        __nv_bfloat16 hi, lo; bsplit(v, hi, lo);
        g_W3hi[j] = hi; g_W3lo[j] = lo;
    }
}

__global__ void conv_x_kernel(const float* __restrict__ x)
{
    size_t idx = (size_t)blockIdx.x * blockDim.x + threadIdx.x;   // float4 idx
    int cv = (int)(idx & 127);
    int m  = (int)(idx >> 7);
    float4 v = *(const float4*)&x[(size_t)m * 512 + cv * 4];
    __nv_bfloat16 h0,l0,h1,l1,h2,l2,h3,l3;
    bsplit(v.x,h0,l0); bsplit(v.y,h1,l1); bsplit(v.z,h2,l2); bsplit(v.w,h3,l3);
    size_t o = (size_t)m * 1024 + 512 + cv * 4;
    *(__nv_bfloat162*)&g_A3hi[o]     = __halves2bfloat162(h0, h1);
    *(__nv_bfloat162*)&g_A3hi[o + 2] = __halves2bfloat162(h2, h3);
    *(__nv_bfloat162*)&g_A3lo[o]     = __halves2bfloat162(l0, l1);
    *(__nv_bfloat162*)&g_A3lo[o + 2] = __halves2bfloat162(l2, l3);
}

// =======================================================================
// HMMA mainloop (CTA 128x256, warp 64x64, K-chunk 32, 3-stage cp.async)
// =======================================================================
__device__ __forceinline__ void issue_chunk(
    uint32_t tb, int tid, int k0,
    const __nv_bfloat16* __restrict__ Ahi, const __nv_bfloat16* __restrict__ Alo, int lda,
    const __nv_bfloat16* __restrict__ Whi, const __nv_bfloat16* __restrict__ Wlo, int ldw)
{
    #pragma unroll
    for (int i = 0; i < 2; ++i) {           // A: 128 rows x 4 x 16B
        int v = i * 256 + tid;
        int r = v >> 2, ch = v & 3;
        uint32_t so = (uint32_t)(r * T_STRIDE + ch * 16);
        int go = k0 + ch * 8;
        cp16(tb +           so, Ahi + (size_t)r * lda + go);
        cp16(tb + A_BYTES + so, Alo + (size_t)r * lda + go);
    }
    #pragma unroll
    for (int i = 0; i < 4; ++i) {           // W: 256 rows x 4 x 16B
        int v = i * 256 + tid;
        int r = v >> 2, ch = v & 3;
        uint32_t so = (uint32_t)(r * T_STRIDE + ch * 16);
        int go = k0 + ch * 8;
        cp16(tb + 2 * A_BYTES +           so, Whi + (size_t)r * ldw + go);
        cp16(tb + 2 * A_BYTES + W_BYTES + so, Wlo + (size_t)r * ldw + go);
    }
    CP_COMMIT();
}

template<int NC>
__device__ __forceinline__ void hmma_mainloop(
    uint32_t sb,
    const __nv_bfloat16* __restrict__ Ahi, const __nv_bfloat16* __restrict__ Alo, int lda,
    const __nv_bfloat16* __restrict__ Whi, const __nv_bfloat16* __restrict__ Wlo, int ldw,
    float acc[4][8][4])
{
    const int tid  = threadIdx.x;
    const int wid  = tid >> 5, lane = tid & 31;
    const int wm   = (wid >> 2) * 64;   // warp m offset: 0 or 64
    const int wn   = (wid & 3) * 64;    // warp n offset: 0,64,128,192
    const uint32_t aSel = (uint32_t)((lane & 15) * T_STRIDE + (lane >> 4) * 16);
    const uint32_t bSel = (uint32_t)((((lane >> 4) << 3) + (lane & 7)) * T_STRIDE
                                     + ((lane >> 3) & 1) * 16);

    issue_chunk(sb,                 tid, 0,  Ahi, Alo, lda, Whi, Wlo, ldw);
    issue_chunk(sb + BUF_BYTES,     tid, 32, Ahi, Alo, lda, Whi, Wlo, ldw);
    issue_chunk(sb + 2 * BUF_BYTES, tid, 64, Ahi, Alo, lda, Whi, Wlo, ldw);

    int buf = 0;
    #pragma unroll 1
    for (int c = 0; c < NC; ++c) {
        if (c + 2 < NC)      { CP_WAIT(2); }
        else if (c + 1 < NC) { CP_WAIT(1); }
        else                 { CP_WAIT(0); }
        __syncthreads();

        const uint32_t tb = sb + (uint32_t)buf * BUF_BYTES;
        const uint32_t At = tb + (uint32_t)wm * T_STRIDE + aSel;
        const uint32_t Wt = tb + 2 * A_BYTES + (uint32_t)wn * T_STRIDE + bSel;

        #pragma unroll
        for (int kk = 0; kk < 2; ++kk) {
            const uint32_t ko = kk * 32;
            uint32_t ah[4][4], al[4][4];
            #pragma unroll
            for (int mb = 0; mb < 4; ++mb) {
                LDSM4(ah[mb][0], ah[mb][1], ah[mb][2], ah[mb][3],
                      At + mb * (16 * T_STRIDE) + ko);
                LDSM4(al[mb][0], al[mb][1], al[mb][2], al[mb][3],
                      At + A_BYTES + mb * (16 * T_STRIDE) + ko);
            }
            #pragma unroll
            for (int nb = 0; nb < 4; ++nb) {
                uint32_t bh[4], bl[4];
                LDSM4(bh[0], bh[1], bh[2], bh[3], Wt + nb * (16 * T_STRIDE) + ko);
                LDSM4(bl[0], bl[1], bl[2], bl[3], Wt + W_BYTES + nb * (16 * T_STRIDE) + ko);
                #pragma unroll
                for (int mb = 0; mb < 4; ++mb) {
                    MMA16816(acc[mb][2 * nb],     ah[mb], bh[0], bh[1]);
                    MMA16816(acc[mb][2 * nb],     ah[mb], bl[0], bl[1]);
                    MMA16816(acc[mb][2 * nb],     al[mb], bh[0], bh[1]);
                    MMA16816(acc[mb][2 * nb + 1], ah[mb], bh[2], bh[3]);
                    MMA16816(acc[mb][2 * nb + 1], ah[mb], bl[2], bl[3]);
                    MMA16816(acc[mb][2 * nb + 1], al[mb], bh[2], bh[3]);
                }
            }
        }
        __syncthreads();
        if (c + 3 < NC)
            issue_chunk(sb + (uint32_t)buf * BUF_BYTES, tid, (c + 3) * 32,
                        Ahi, Alo, lda, Whi, Wlo, ldw);
        buf = (buf == NSTAGE - 1) ? 0 : buf + 1;
    }
}

// =======================================================================
// Stage 1: raw = x @ W1^T (M=32768, N=1024, K=512) -> a,b coefs + chunk P,Q
// grid (4, 256); blockIdx.y == chunk id (chunks align with 128-row M tiles)
// =======================================================================
__global__ __launch_bounds__(256, 1)
void hmma_stage1_kernel(const float* __restrict__ Avec,
                        const float* __restrict__ bias_h)
{
    extern __shared__ __align__(16) char smem[];
    const uint32_t sb = smem_u32(smem);

    float acc[4][8][4];
    #pragma unroll
    for (int i = 0; i < 4; ++i)
        #pragma unroll
        for (int j = 0; j < 8; ++j)
            #pragma unroll
            for (int q = 0; q < 4; ++q) acc[i][j][q] = 0.f;

    const int row0 = blockIdx.y * 128;
    const int col0 = blockIdx.x * 256;

    hmma_mainloop<16>(sb,
                      g_A3hi + 512 + (size_t)row0 * 1024,
                      g_A3lo + 512 + (size_t)row0 * 1024, 1024,
                      g_W1hi + (size_t)col0 * 512,
                      g_W1lo + (size_t)col0 * 512, 512,
                      acc);

    const int tid = threadIdx.x, wid = tid >> 5, lane = tid & 31;
    const int wm = (wid >> 2) * 64, wn = (wid & 3) * 64;
    const int g = lane >> 2, tig = lane & 3;
    const int hbase = col0 >> 1;

    float* sA = (float*)smem;              // [128][129]
    float* sB = sA + 128 * 129;

    #pragma unroll
    for (int mb = 0; mb < 4; ++mb) {
        #pragma unroll
        for (int j = 0; j < 8; ++j) {
            int n0 = wn + (j >> 1) * 16 + (j & 1) * 8 + 2 * tig;   // even
            int h_loc = n0 >> 1;
            int hg = hbase + h_loc;
            float Ah = Avec[hg], Bh = bias_h[hg];
            int m0 = wm + mb * 16 + g;

            float g0 = 1.0f / (1.0f + __expf(-acc[mb][j][0]));
            g0 = fminf(fmaxf(g0, 0.05f), 0.95f);
            sA[m0 * 129 + h_loc] = 1.0f - g0 * (1.0f - Ah);
            sB[m0 * 129 + h_loc] = g0 * (acc[mb][j][1] + Bh);

            float g1 = 1.0f / (1.0f + __expf(-acc[mb][j][2]));
            g1 = fminf(fmaxf(g1, 0.05f), 0.95f);
            sA[(m0 + 8) * 129 + h_loc] = 1.0f - g1 * (1.0f - Ah);
            sB[(m0 + 8) * 129 + h_loc] = g1 * (acc[mb][j][3] + Bh);
        }
    }
    __syncthreads();

    // coalesced global write of a,b
    const int nn = tid & 127, rg = tid >> 7;
    #pragma unroll
    for (int r = 0; r < 64; ++r) {
        int row = rg * 64 + r;
        size_t gb = (size_t)(row0 + row) * DIM + hbase + nn;
        g_a[gb] = sA[row * 129 + nn];
        g_b[gb] = sB[row * 129 + nn];
    }

    // chunk summaries: P = prod(a), Q = local-scan final value (h_in = 0)
    if (tid < 128) {
        float p = 1.0f, q = 0.0f;
        #pragma unroll 4
        for (int r = 0; r < 128; ++r) {
            float a  = sA[r * 129 + tid];
            float bb = sB[r * 129 + tid];
            q = fmaf(a, q, bb);
            p *= a;
        }
        size_t o = (size_t)blockIdx.y * DIM + hbase + tid;
        g_P[o] = p;
        g_Q[o] = q;
    }
}

// =======================================================================
// carry: h_in[c] from chunk summaries (8 blocks x 512 threads)
// =======================================================================
__global__ __launch_bounds__(512) void scan_carry_kernel()
{
    const int b = blockIdx.x;
    const int h = threadIdx.x;
    float hin = 0.0f;
    #pragma unroll
    for (int c = 0; c < NCHUNK; ++c) {
        const size_t o = ((size_t)b * NCHUNK + c) * DIM + h;
        g_Hin[o] = hin;
        hin = fmaf(g_P[o], hin, g_Q[o]);
    }
}

// =======================================================================
// final scan: recompute exact fp32 recurrence with carry-in, emit bf16 hi/lo
// directly into A3 columns [0,512). grid 256 x 512.
// =======================================================================
__global__ __launch_bounds__(512) void scan_final_kernel()
{
    const int bc = blockIdx.x;
    const int b  = bc / NCHUNK;
    const int c  = bc % NCHUNK;
    const int h  = threadIdx.x;
    const size_t base = ((size_t)b * SEQLEN + (size_t)c * CHUNK) * DIM + h;

    float hcur = g_Hin[(size_t)bc * DIM + h];
    #pragma unroll 4
    for (int t = 0; t < CHUNK; ++t) {
        const size_t off = base + (size_t)t * DIM;
        hcur = fmaf(g_a[off], hcur, g_b[off]);
        __nv_bfloat16 hi, lo; bsplit(hcur, hi, lo);
        const size_t m = (size_t)(b * SEQLEN + c * CHUNK + t);
        g_A3hi[m * 1024 + h] = hi;
        g_A3lo[m * 1024 + h] = lo;
    }
}

// =======================================================================
// Stage 3: y = (hs@C^T + x@D^T + bias_y)*scale, K=1024 fused GEMM
// grid (2, 256)
// =======================================================================
__global__ __launch_bounds__(256, 1)
void hmma_stage3_kernel(const float* __restrict__ bias_y, float* __restrict__ out)
{
    extern __shared__ __align__(16) char smem[];
    const uint32_t sb = smem_u32(smem);

    float acc[4][8][4];
    #pragma unroll
    for (int i = 0; i < 4; ++i)
        #pragma unroll
        for (int j = 0; j < 8; ++j)
            #pragma unroll
            for (int q = 0; q < 4; ++q) acc[i][j][q] = 0.f;

    const int row0 = blockIdx.y * 128;
    const int col0 = blockIdx.x * 256;

    hmma_mainloop<32>(sb,
                      g_A3hi + (size_t)row0 * 1024,
                      g_A3lo + (size_t)row0 * 1024, 1024,
                      g_W3hi + (size_t)col0 * 1024,
                      g_W3lo + (size_t)col0 * 1024, 1024,
                      acc);

    const int tid = threadIdx.x, wid = tid >> 5, lane = tid & 31;
    const int wm = (wid >> 2) * 64, wn = (wid & 3) * 64;
    const int g = lane >> 2, tig = lane & 3;
    const float scale = 0.04419417382415922f;   // 1/sqrt(512)

    float* sY = (float*)smem;                   // [128][257]

    #pragma unroll
    for (int mb = 0; mb < 4; ++mb) {
        #pragma unroll
        for (int j = 0; j < 8; ++j) {
            int n0 = wn + (j >> 1) * 16 + (j & 1) * 8 + 2 * tig;
            float by0 = bias_y[col0 + n0], by1 = bias_y[col0 + n0 + 1];
            int m0 = wm + mb * 16 + g;
            sY[m0 * 257 + n0]           = (acc[mb][j][0] + by0) * scale;
            sY[m0 * 257 + n0 + 1]       = (acc[mb][j][1] + by1) * scale;
            sY[(m0 + 8) * 257 + n0]     = (acc[mb][j][2] + by0) * scale;
            sY[(m0 + 8) * 257 + n0 + 1] = (acc[mb][j][3] + by1) * scale;
        }
    }
    __syncthreads();

    const int nn = tid;                         // 256 cols, 256 threads
    #pragma unroll 4
    for (int r = 0; r < 128; ++r)
        out[(size_t)(row0 + r) * DIM + col0 + nn] = sY[r * 257 + nn];
}

// =======================================================================
extern "C" void kernel_launch(void* const* d_in, const int* in_sizes, int n_in,
                              void* d_out, int out_size)
{
    const float* x      = (const float*)d_in[0];
    const float* Avec   = (const float*)d_in[1];
    const float* B      = (const float*)d_in[2];
    const float* C      = (const float*)d_in[3];
    const float* Dm     = (const float*)d_in[4];
    const float* Wg     = (const float*)d_in[5];
    const float* bias_h = (const float*)d_in[6];
    const float* bias_y = (const float*)d_in[7];
    float* out = (float*)d_out;

    cudaFuncSetAttribute(hmma_stage1_kernel,
                         cudaFuncAttributeMaxDynamicSharedMemorySize, SMEM_REQ);
    cudaFuncSetAttribute(hmma_stage3_kernel,
                         cudaFuncAttributeMaxDynamicSharedMemorySize, SMEM_REQ);

    conv_w_kernel<<<(1024 * 512 + 512 * 1024) / 256, 256>>>(Wg, B, C, Dm);
    conv_x_kernel<<<(MROWS * (DIM / 4)) / 256, 256>>>(x);

    hmma_stage1_kernel<<<dim3(4, MROWS / 128), 256, SMEM_REQ>>>(Avec, bias_h);

    scan_carry_kernel<<<BATCH, 512>>>();
    scan_final_kernel<<<BATCH * NCHUNK, 512>>>();

    hmma_stage3_kernel<<<dim3(2, MROWS / 128), 256, SMEM_REQ>>>(bias_y, out);
}

// round 7
// speedup vs baseline: 1.1061x; 1.1061x over previous
#include <cuda_runtime.h>
#include <cuda_bf16.h>
#include <math.h>
#include <stdint.h>

#define BATCH   8
#define SEQLEN  4096
#define DIM     512
#define MROWS   (BATCH * SEQLEN)   // 32768
#define CHUNK   128
#define NCHUNK  (SEQLEN / CHUNK)   // 32

// ================= static scratch =================
__device__ float g_a  [(size_t)MROWS * DIM];
__device__ float g_b  [(size_t)MROWS * DIM];
__device__ float g_Hin[BATCH * NCHUNK * DIM];
__device__ float g_P  [BATCH * NCHUNK * DIM];
__device__ float g_Q  [BATCH * NCHUNK * DIM];

// bf16 split operands. A3 = [hs | x] : 32768 x 1024
__device__ __align__(16) __nv_bfloat16 g_A3hi[(size_t)MROWS * 1024];
__device__ __align__(16) __nv_bfloat16 g_A3lo[(size_t)MROWS * 1024];
__device__ __align__(16) __nv_bfloat16 g_W1hi[1024 * 512];   // interleaved [Wg;B]
__device__ __align__(16) __nv_bfloat16 g_W1lo[1024 * 512];
__device__ __align__(16) __nv_bfloat16 g_W3hi[512 * 1024];   // [C | D]
__device__ __align__(16) __nv_bfloat16 g_W3lo[512 * 1024];

// ================= PTX helpers (sm_80+ family-safe) ========
__device__ __forceinline__ uint32_t smem_u32(const void* p) {
    uint32_t a;
    asm("{ .reg .u64 t; cvta.to.shared.u64 t, %1; cvt.u32.u64 %0, t; }"
        : "=r"(a) : "l"(p));
    return a;
}
__device__ __forceinline__ void cp16(uint32_t s, const void* g) {
    asm volatile("cp.async.cg.shared.global [%0], [%1], 16;"
                 :: "r"(s), "l"(__cvta_generic_to_global(g)) : "memory");
}
#define CP_COMMIT() asm volatile("cp.async.commit_group;" ::: "memory")
#define CP_WAIT(n)  asm volatile("cp.async.wait_group %0;" :: "n"(n) : "memory")

#define LDSM4(r0, r1, r2, r3, addr) \
    asm volatile("ldmatrix.sync.aligned.m8n8.x4.shared.b16 {%0,%1,%2,%3}, [%4];" \
                 : "=r"(r0), "=r"(r1), "=r"(r2), "=r"(r3) : "r"(addr))

#define MMA16816(c, a, b0, b1) \
    asm volatile("mma.sync.aligned.m16n8k16.row.col.f32.bf16.bf16.f32 " \
                 "{%0,%1,%2,%3}, {%4,%5,%6,%7}, {%8,%9}, {%0,%1,%2,%3};" \
                 : "+f"((c)[0]), "+f"((c)[1]), "+f"((c)[2]), "+f"((c)[3]) \
                 : "r"((a)[0]), "r"((a)[1]), "r"((a)[2]), "r"((a)[3]), \
                   "r"(b0), "r"(b1))

// smem tile geometry: 128 rows x 32 bf16 data, row stride 80B (conflict-free
// for ldmatrix: 80*r mod 128 covers all eight 16B slots over r=0..7).
#define T_STRIDE 80
#define T_BYTES  (128 * T_STRIDE)          // 10240
#define BUF_BYTES (4 * T_BYTES)            // Ahi,Alo,Whi,Wlo = 40960
#define SMEM_REQ  (2 * BUF_BYTES)          // 81920 (double buffer, occ 2)

// ================= bf16 split =================
__device__ __forceinline__ void bsplit(float v, __nv_bfloat16& hi, __nv_bfloat16& lo) {
    hi = __float2bfloat16_rn(v);
    lo = __float2bfloat16_rn(v - __bfloat162float(hi));
}

// =======================================================================
// conv kernels
// =======================================================================
__global__ void conv_w_kernel(const float* __restrict__ Wg, const float* __restrict__ B,
                              const float* __restrict__ C,  const float* __restrict__ D)
{
    int idx = blockIdx.x * blockDim.x + threadIdx.x;
    if (idx < 1024 * 512) {
        int r = idx >> 9, k = idx & 511, h = r >> 1;
        float v = (r & 1) ? B[h * 512 + k] : Wg[h * 512 + k];
        __nv_bfloat16 hi, lo; bsplit(v, hi, lo);
        g_W1hi[idx] = hi; g_W1lo[idx] = lo;
    } else {
        int j = idx - 1024 * 512;
        int n = j >> 10, k = j & 1023;
        float v = (k < 512) ? C[n * 512 + k] : D[n * 512 + k - 512];
        __nv_bfloat16 hi, lo; bsplit(v, hi, lo);
        g_W3hi[j] = hi; g_W3lo[j] = lo;
    }
}

__global__ void conv_x_kernel(const float* __restrict__ x)
{
    size_t idx = (size_t)blockIdx.x * blockDim.x + threadIdx.x;   // float4 idx
    int cv = (int)(idx & 127);
    int m  = (int)(idx >> 7);
    float4 v = *(const float4*)&x[(size_t)m * 512 + cv * 4];
    __nv_bfloat16 h0,l0,h1,l1,h2,l2,h3,l3;
    bsplit(v.x,h0,l0); bsplit(v.y,h1,l1); bsplit(v.z,h2,l2); bsplit(v.w,h3,l3);
    size_t o = (size_t)m * 1024 + 512 + cv * 4;
    *(__nv_bfloat162*)&g_A3hi[o]     = __halves2bfloat162(h0, h1);
    *(__nv_bfloat162*)&g_A3hi[o + 2] = __halves2bfloat162(h2, h3);
    *(__nv_bfloat162*)&g_A3lo[o]     = __halves2bfloat162(l0, l1);
    *(__nv_bfloat162*)&g_A3lo[o + 2] = __halves2bfloat162(l2, l3);
}

// =======================================================================
// HMMA mainloop (R4 config: CTA 128x128, warp 32x64, 2-stage cp.async)
// =======================================================================
__device__ __forceinline__ void issue_chunk(
    uint32_t tb, int tid, int k0,
    const __nv_bfloat16* __restrict__ Ahi, const __nv_bfloat16* __restrict__ Alo, int lda,
    const __nv_bfloat16* __restrict__ Whi, const __nv_bfloat16* __restrict__ Wlo, int ldw)
{
    #pragma unroll
    for (int i = 0; i < 2; ++i) {
        int idx = i * 256 + tid;
        int r = idx >> 2, ch = idx & 3;
        uint32_t so = (uint32_t)(r * T_STRIDE + ch * 16);
        int go = k0 + ch * 8;
        cp16(tb +               so, Ahi + (size_t)r * lda + go);
        cp16(tb +     T_BYTES + so, Alo + (size_t)r * lda + go);
        cp16(tb + 2 * T_BYTES + so, Whi + (size_t)r * ldw + go);
        cp16(tb + 3 * T_BYTES + so, Wlo + (size_t)r * ldw + go);
    }
    CP_COMMIT();
}

template<int NC>
__device__ __forceinline__ void hmma_mainloop(
    uint32_t sb,
    const __nv_bfloat16* __restrict__ Ahi, const __nv_bfloat16* __restrict__ Alo, int lda,
    const __nv_bfloat16* __restrict__ Whi, const __nv_bfloat16* __restrict__ Wlo, int ldw,
    float acc[2][8][4])
{
    const int tid  = threadIdx.x;
    const int wid  = tid >> 5, lane = tid & 31;
    const int wm   = (wid >> 1) * 32;       // warp m offset (0..96)
    const int wn   = (wid & 1) * 64;        // warp n offset (0 or 64)
    const uint32_t aSel = (uint32_t)((lane & 15) * T_STRIDE + (lane >> 4) * 16);
    const uint32_t bSel = (uint32_t)((((lane >> 4) << 3) + (lane & 7)) * T_STRIDE
                                     + ((lane >> 3) & 1) * 16);

    issue_chunk(sb,             tid, 0,  Ahi, Alo, lda, Whi, Wlo, ldw);
    issue_chunk(sb + BUF_BYTES, tid, 32, Ahi, Alo, lda, Whi, Wlo, ldw);

    #pragma unroll 1
    for (int c = 0; c < NC; ++c) {
        if (c + 1 == NC) { CP_WAIT(0); } else { CP_WAIT(1); }
        __syncthreads();

        const uint32_t tb = sb + (uint32_t)(c & 1) * BUF_BYTES;
        const uint32_t At = tb + (uint32_t)wm * T_STRIDE + aSel;
        const uint32_t Wt = tb + 2 * T_BYTES + (uint32_t)wn * T_STRIDE + bSel;

        #pragma unroll
        for (int kk = 0; kk < 2; ++kk) {
            const uint32_t ko = kk * 32;    // 16 bf16 = 32B per k16 step
            uint32_t ah[2][4], al[2][4];
            #pragma unroll
            for (int mb = 0; mb < 2; ++mb) {
                LDSM4(ah[mb][0], ah[mb][1], ah[mb][2], ah[mb][3],
                      At + mb * (16 * T_STRIDE) + ko);
                LDSM4(al[mb][0], al[mb][1], al[mb][2], al[mb][3],
                      At + T_BYTES + mb * (16 * T_STRIDE) + ko);
            }
            #pragma unroll
            for (int nb = 0; nb < 4; ++nb) {
                uint32_t bh[4], bl[4];
                LDSM4(bh[0], bh[1], bh[2], bh[3], Wt + nb * (16 * T_STRIDE) + ko);
                LDSM4(bl[0], bl[1], bl[2], bl[3], Wt + T_BYTES + nb * (16 * T_STRIDE) + ko);
                #pragma unroll
                for (int mb = 0; mb < 2; ++mb) {
                    MMA16816(acc[mb][2 * nb],     ah[mb], bh[0], bh[1]);
                    MMA16816(acc[mb][2 * nb],     ah[mb], bl[0], bl[1]);
                    MMA16816(acc[mb][2 * nb],     al[mb], bh[0], bh[1]);
                    MMA16816(acc[mb][2 * nb + 1], ah[mb], bh[2], bh[3]);
                    MMA16816(acc[mb][2 * nb + 1], ah[mb], bl[2], bl[3]);
                    MMA16816(acc[mb][2 * nb + 1], al[mb], bh[2], bh[3]);
                }
            }
        }
        __syncthreads();
        if (c + 2 < NC)
            issue_chunk(sb + (uint32_t)(c & 1) * BUF_BYTES, tid, (c + 2) * 32,
                        Ahi, Alo, lda, Whi, Wlo, ldw);
    }
}

// =======================================================================
// Stage 1: raw = x @ W1^T (M=32768, N=1024, K=512) -> a,b coefs + chunk P,Q
// grid (8, 256): blockIdx.y = global chunk id (M tile == one t-chunk)
// =======================================================================
__global__ __launch_bounds__(256, 2)
void hmma_stage1_kernel(const float* __restrict__ Avec,
                        const float* __restrict__ bias_h)
{
    extern __shared__ __align__(16) char smem[];
    const uint32_t sb = smem_u32(smem);

    float acc[2][8][4];
    #pragma unroll
    for (int i = 0; i < 2; ++i)
        #pragma unroll
        for (int j = 0; j < 8; ++j)
            #pragma unroll
            for (int q = 0; q < 4; ++q) acc[i][j][q] = 0.f;

    const int row0 = blockIdx.y * 128;
    const int col0 = blockIdx.x * 128;

    hmma_mainloop<16>(sb,
                      g_A3hi + 512 + (size_t)row0 * 1024,
                      g_A3lo + 512 + (size_t)row0 * 1024, 1024,
                      g_W1hi + (size_t)col0 * 512,
                      g_W1lo + (size_t)col0 * 512, 512,
                      acc);

    // -------- epilogue: gate math in-lane (pair cols), smem restage --------
    const int tid = threadIdx.x, wid = tid >> 5, lane = tid & 31;
    const int wm = (wid >> 1) * 32, wn = (wid & 1) * 64;
    const int g = lane >> 2, tig = lane & 3;
    const int hbase = col0 >> 1;

    float* sA = (float*)smem;              // [128][65]
    float* sB = sA + 128 * 65;             // [128][65]

    #pragma unroll
    for (int mb = 0; mb < 2; ++mb) {
        #pragma unroll
        for (int j = 0; j < 8; ++j) {
            int h_loc = (wn + (j >> 1) * 16 + (j & 1) * 8 + 2 * tig) >> 1;
            int hg = hbase + h_loc;
            float Ah = Avec[hg], Bh = bias_h[hg];
            int m0 = wm + mb * 16 + g;

            float z0 = acc[mb][j][0], x0 = acc[mb][j][1];
            float g0 = 1.0f / (1.0f + __expf(-z0));
            g0 = fminf(fmaxf(g0, 0.05f), 0.95f);
            sA[m0 * 65 + h_loc] = 1.0f - g0 * (1.0f - Ah);
            sB[m0 * 65 + h_loc] = g0 * (x0 + Bh);

            float z1 = acc[mb][j][2], x1 = acc[mb][j][3];
            float g1 = 1.0f / (1.0f + __expf(-z1));
            g1 = fminf(fmaxf(g1, 0.05f), 0.95f);
            sA[(m0 + 8) * 65 + h_loc] = 1.0f - g1 * (1.0f - Ah);
            sB[(m0 + 8) * 65 + h_loc] = g1 * (x1 + Bh);
        }
    }
    __syncthreads();

    // coalesced global write of a,b
    const int hh = tid & 63, rg = tid >> 6;
    #pragma unroll
    for (int r = 0; r < 32; ++r) {
        int row = rg * 32 + r;
        size_t gb = (size_t)(row0 + row) * DIM + hbase + hh;
        g_a[gb] = sA[row * 65 + hh];
        g_b[gb] = sB[row * 65 + hh];
    }

    // chunk summaries from smem: P = prod(a), Q = local-scan final (h_in = 0)
    if (tid < 64) {
        float p = 1.0f, q = 0.0f;
        #pragma unroll 4
        for (int r = 0; r < 128; ++r) {
            float a  = sA[r * 65 + tid];
            float bb = sB[r * 65 + tid];
            q = fmaf(a, q, bb);
            p *= a;
        }
        size_t o = (size_t)blockIdx.y * DIM + hbase + tid;
        g_P[o] = p;
        g_Q[o] = q;
    }
}

// =======================================================================
// carry: h_in per chunk from summaries (8 blocks x 512 threads)
// =======================================================================
__global__ __launch_bounds__(512) void scan_carry_kernel()
{
    const int b = blockIdx.x;
    const int h = threadIdx.x;
    float hin = 0.0f;
    #pragma unroll
    for (int c = 0; c < NCHUNK; ++c) {
        const size_t o = ((size_t)b * NCHUNK + c) * DIM + h;
        g_Hin[o] = hin;
        hin = fmaf(g_P[o], hin, g_Q[o]);
    }
}

// =======================================================================
// final scan: exact fp32 recurrence with carry-in, emit bf16 hi/lo into A3
// =======================================================================
__global__ __launch_bounds__(512) void scan_final_kernel()
{
    const int bc = blockIdx.x;
    const int b  = bc / NCHUNK;
    const int c  = bc % NCHUNK;
    const int h  = threadIdx.x;
    const size_t base = ((size_t)b * SEQLEN + (size_t)c * CHUNK) * DIM + h;

    float hcur = g_Hin[(size_t)bc * DIM + h];
    #pragma unroll 4
    for (int t = 0; t < CHUNK; ++t) {
        const size_t off = base + (size_t)t * DIM;
        hcur = fmaf(g_a[off], hcur, g_b[off]);
        __nv_bfloat16 hi, lo; bsplit(hcur, hi, lo);
        const size_t m = (size_t)(b * SEQLEN + c * CHUNK + t);
        g_A3hi[m * 1024 + h] = hi;
        g_A3lo[m * 1024 + h] = lo;
    }
}

// =======================================================================
// Stage 3: y = (hs@C^T + x@D^T + bias_y)*scale, K=1024 fused GEMM
// grid (4, 256)
// =======================================================================
__global__ __launch_bounds__(256, 2)
void hmma_stage3_kernel(const float* __restrict__ bias_y, float* __restrict__ out)
{
    extern __shared__ __align__(16) char smem[];
    const uint32_t sb = smem_u32(smem);

    float acc[2][8][4];
    #pragma unroll
    for (int i = 0; i < 2; ++i)
        #pragma unroll
        for (int j = 0; j < 8; ++j)
            #pragma unroll
            for (int q = 0; q < 4; ++q) acc[i][j][q] = 0.f;

    const int row0 = blockIdx.y * 128;
    const int col0 = blockIdx.x * 128;

    hmma_mainloop<32>(sb,
                      g_A3hi + (size_t)row0 * 1024,
                      g_A3lo + (size_t)row0 * 1024, 1024,
                      g_W3hi + (size_t)col0 * 1024,
                      g_W3lo + (size_t)col0 * 1024, 1024,
                      acc);

    const int tid = threadIdx.x, wid = tid >> 5, lane = tid & 31;
    const int wm = (wid >> 1) * 32, wn = (wid & 1) * 64;
    const int g = lane >> 2, tig = lane & 3;
    const float scale = 0.04419417382415922f;   // 1/sqrt(512)

    float* sY = (float*)smem;                   // [128][129]

    #pragma unroll
    for (int mb = 0; mb < 2; ++mb) {
        #pragma unroll
        for (int j = 0; j < 8; ++j) {
            int n0 = wn + (j >> 1) * 16 + (j & 1) * 8 + 2 * tig;
            float by0 = bias_y[col0 + n0], by1 = bias_y[col0 + n0 + 1];
            int m0 = wm + mb * 16 + g;
            sY[m0 * 129 + n0]           = (acc[mb][j][0] + by0) * scale;
            sY[m0 * 129 + n0 + 1]       = (acc[mb][j][1] + by1) * scale;
            sY[(m0 + 8) * 129 + n0]     = (acc[mb][j][2] + by0) * scale;
            sY[(m0 + 8) * 129 + n0 + 1] = (acc[mb][j][3] + by1) * scale;
        }
    }
    __syncthreads();

    const int nn = tid & 127, rg = tid >> 7;
    #pragma unroll
    for (int r = 0; r < 64; ++r) {
        int row = rg * 64 + r;
        out[(size_t)(row0 + row) * DIM + col0 + nn] = sY[row * 129 + nn];
    }
}

// =======================================================================
extern "C" void kernel_launch(void* const* d_in, const int* in_sizes, int n_in,
                              void* d_out, int out_size)
{
    const float* x      = (const float*)d_in[0];
    const float* Avec   = (const float*)d_in[1];
    const float* B      = (const float*)d_in[2];
    const float* C      = (const float*)d_in[3];
    const float* Dm     = (const float*)d_in[4];
    const float* Wg     = (const float*)d_in[5];
    const float* bias_h = (const float*)d_in[6];
    const float* bias_y = (const float*)d_in[7];
    float* out = (float*)d_out;

    cudaFuncSetAttribute(hmma_stage1_kernel,
                         cudaFuncAttributeMaxDynamicSharedMemorySize, SMEM_REQ);
    cudaFuncSetAttribute(hmma_stage3_kernel,
                         cudaFuncAttributeMaxDynamicSharedMemorySize, SMEM_REQ);

    conv_w_kernel<<<(1024 * 512 + 512 * 1024) / 256, 256>>>(Wg, B, C, Dm);
    conv_x_kernel<<<(MROWS * (DIM / 4)) / 256, 256>>>(x);

    hmma_stage1_kernel<<<dim3(8, MROWS / 128), 256, SMEM_REQ>>>(Avec, bias_h);

    scan_carry_kernel<<<BATCH, 512>>>();
    scan_final_kernel<<<BATCH * NCHUNK, 512>>>();

    hmma_stage3_kernel<<<dim3(4, MROWS / 128), 256, SMEM_REQ>>>(bias_y, out);
}

// round 8
// speedup vs baseline: 1.1300x; 1.0216x over previous
#include <cuda_runtime.h>
#include <cuda_bf16.h>
#include <math.h>
#include <stdint.h>

#define BATCH   8
#define SEQLEN  4096
#define DIM     512
#define MROWS   (BATCH * SEQLEN)   // 32768
#define CHUNK   128
#define NCHUNK  (SEQLEN / CHUNK)   // 32

// ================= static scratch =================
__device__ float g_a  [(size_t)MROWS * DIM];
__device__ float g_b  [(size_t)MROWS * DIM];
__device__ float g_P  [BATCH * NCHUNK * DIM];
__device__ float g_Q  [BATCH * NCHUNK * DIM];

// bf16 split operands. A3 = [hs | x] : 32768 x 1024
__device__ __align__(16) __nv_bfloat16 g_A3hi[(size_t)MROWS * 1024];
__device__ __align__(16) __nv_bfloat16 g_A3lo[(size_t)MROWS * 1024];
__device__ __align__(16) __nv_bfloat16 g_W1hi[1024 * 512];   // interleaved [Wg;B]
__device__ __align__(16) __nv_bfloat16 g_W1lo[1024 * 512];
__device__ __align__(16) __nv_bfloat16 g_W3hi[512 * 1024];   // [C | D]
__device__ __align__(16) __nv_bfloat16 g_W3lo[512 * 1024];

// ================= PTX helpers (sm_80+ family-safe) ========
__device__ __forceinline__ uint32_t smem_u32(const void* p) {
    uint32_t a;
    asm("{ .reg .u64 t; cvta.to.shared.u64 t, %1; cvt.u32.u64 %0, t; }"
        : "=r"(a) : "l"(p));
    return a;
}
__device__ __forceinline__ void cp16(uint32_t s, const void* g) {
    asm volatile("cp.async.cg.shared.global [%0], [%1], 16;"
                 :: "r"(s), "l"(__cvta_generic_to_global(g)) : "memory");
}
#define CP_COMMIT() asm volatile("cp.async.commit_group;" ::: "memory")
#define CP_WAIT(n)  asm volatile("cp.async.wait_group %0;" :: "n"(n) : "memory")

#define LDSM4(r0, r1, r2, r3, addr) \
    asm volatile("ldmatrix.sync.aligned.m8n8.x4.shared.b16 {%0,%1,%2,%3}, [%4];" \
                 : "=r"(r0), "=r"(r1), "=r"(r2), "=r"(r3) : "r"(addr))

#define MMA16816(c, a, b0, b1) \
    asm volatile("mma.sync.aligned.m16n8k16.row.col.f32.bf16.bf16.f32 " \
                 "{%0,%1,%2,%3}, {%4,%5,%6,%7}, {%8,%9}, {%0,%1,%2,%3};" \
                 : "+f"((c)[0]), "+f"((c)[1]), "+f"((c)[2]), "+f"((c)[3]) \
                 : "r"((a)[0]), "r"((a)[1]), "r"((a)[2]), "r"((a)[3]), \
                   "r"(b0), "r"(b1))

// smem tile geometry: 128 rows x 32 bf16 data, row stride 80B (ldmatrix conflict-free)
#define T_STRIDE 80
#define T_BYTES  (128 * T_STRIDE)          // 10240
#define BUF_BYTES (4 * T_BYTES)            // Ahi,Alo,Whi,Wlo = 40960
#define SMEM_REQ  (2 * BUF_BYTES)          // 81920 (double buffer, 2 CTAs/SM)

// ================= bf16 split =================
__device__ __forceinline__ void bsplit(float v, __nv_bfloat16& hi, __nv_bfloat16& lo) {
    hi = __float2bfloat16_rn(v);
    lo = __float2bfloat16_rn(v - __bfloat162float(hi));
}

// =======================================================================
// conv kernels
// =======================================================================
__global__ void conv_w_kernel(const float* __restrict__ Wg, const float* __restrict__ B,
                              const float* __restrict__ C,  const float* __restrict__ D)
{
    int idx = blockIdx.x * blockDim.x + threadIdx.x;
    if (idx < 1024 * 512) {
        int r = idx >> 9, k = idx & 511, h = r >> 1;
        float v = (r & 1) ? B[h * 512 + k] : Wg[h * 512 + k];
        __nv_bfloat16 hi, lo; bsplit(v, hi, lo);
        g_W1hi[idx] = hi; g_W1lo[idx] = lo;
    } else {
        int j = idx - 1024 * 512;
        int n = j >> 10, k = j & 1023;
        float v = (k < 512) ? C[n * 512 + k] : D[n * 512 + k - 512];
        __nv_bfloat16 hi, lo; bsplit(v, hi, lo);
        g_W3hi[j] = hi; g_W3lo[j] = lo;
    }
}

__global__ void conv_x_kernel(const float* __restrict__ x)
{
    size_t idx = (size_t)blockIdx.x * blockDim.x + threadIdx.x;   // float4 idx
    int cv = (int)(idx & 127);
    int m  = (int)(idx >> 7);
    float4 v = *(const float4*)&x[(size_t)m * 512 + cv * 4];
    __nv_bfloat16 h0,l0,h1,l1,h2,l2,h3,l3;
    bsplit(v.x,h0,l0); bsplit(v.y,h1,l1); bsplit(v.z,h2,l2); bsplit(v.w,h3,l3);
    size_t o = (size_t)m * 1024 + 512 + cv * 4;
    *(__nv_bfloat162*)&g_A3hi[o]     = __halves2bfloat162(h0, h1);
    *(__nv_bfloat162*)&g_A3hi[o + 2] = __halves2bfloat162(h2, h3);
    *(__nv_bfloat162*)&g_A3lo[o]     = __halves2bfloat162(l0, l1);
    *(__nv_bfloat162*)&g_A3lo[o + 2] = __halves2bfloat162(l2, l3);
}

// =======================================================================
// HMMA mainloop: CTA 128x128, 4 warps, warp tile 64x64, 2-stage cp.async
// =======================================================================
__device__ __forceinline__ void issue_chunk(
    uint32_t tb, int tid, int k0,
    const __nv_bfloat16* __restrict__ Ahi, const __nv_bfloat16* __restrict__ Alo, int lda,
    const __nv_bfloat16* __restrict__ Whi, const __nv_bfloat16* __restrict__ Wlo, int ldw)
{
    #pragma unroll
    for (int i = 0; i < 4; ++i) {
        int v = i * 128 + tid;              // 0..511
        int r = v >> 2, ch = v & 3;
        uint32_t so = (uint32_t)(r * T_STRIDE + ch * 16);
        int go = k0 + ch * 8;
        cp16(tb +               so, Ahi + (size_t)r * lda + go);
        cp16(tb +     T_BYTES + so, Alo + (size_t)r * lda + go);
        cp16(tb + 2 * T_BYTES + so, Whi + (size_t)r * ldw + go);
        cp16(tb + 3 * T_BYTES + so, Wlo + (size_t)r * ldw + go);
    }
    CP_COMMIT();
}

template<int NC>
__device__ __forceinline__ void hmma_mainloop(
    uint32_t sb,
    const __nv_bfloat16* __restrict__ Ahi, const __nv_bfloat16* __restrict__ Alo, int lda,
    const __nv_bfloat16* __restrict__ Whi, const __nv_bfloat16* __restrict__ Wlo, int ldw,
    float acc[4][8][4])
{
    const int tid  = threadIdx.x;
    const int wid  = tid >> 5, lane = tid & 31;
    const int wm   = (wid >> 1) * 64;       // warp m offset: 0 or 64
    const int wn   = (wid & 1) * 64;        // warp n offset: 0 or 64
    const uint32_t aSel = (uint32_t)((lane & 15) * T_STRIDE + (lane >> 4) * 16);
    const uint32_t bSel = (uint32_t)((((lane >> 4) << 3) + (lane & 7)) * T_STRIDE
                                     + ((lane >> 3) & 1) * 16);

    issue_chunk(sb,             tid, 0,  Ahi, Alo, lda, Whi, Wlo, ldw);
    issue_chunk(sb + BUF_BYTES, tid, 32, Ahi, Alo, lda, Whi, Wlo, ldw);

    #pragma unroll 1
    for (int c = 0; c < NC; ++c) {
        if (c + 1 == NC) { CP_WAIT(0); } else { CP_WAIT(1); }
        __syncthreads();

        const uint32_t tb = sb + (uint32_t)(c & 1) * BUF_BYTES;
        const uint32_t At = tb + (uint32_t)wm * T_STRIDE + aSel;
        const uint32_t Wt = tb + 2 * T_BYTES + (uint32_t)wn * T_STRIDE + bSel;

        #pragma unroll
        for (int kk = 0; kk < 2; ++kk) {
            const uint32_t ko = kk * 32;    // 16 bf16 = 32B per k16 step
            uint32_t ah[4][4], al[4][4];
            #pragma unroll
            for (int mb = 0; mb < 4; ++mb) {
                LDSM4(ah[mb][0], ah[mb][1], ah[mb][2], ah[mb][3],
                      At + mb * (16 * T_STRIDE) + ko);
                LDSM4(al[mb][0], al[mb][1], al[mb][2], al[mb][3],
                      At + T_BYTES + mb * (16 * T_STRIDE) + ko);
            }
            #pragma unroll
            for (int nb = 0; nb < 4; ++nb) {
                uint32_t bh[4], bl[4];
                LDSM4(bh[0], bh[1], bh[2], bh[3], Wt + nb * (16 * T_STRIDE) + ko);
                LDSM4(bl[0], bl[1], bl[2], bl[3], Wt + T_BYTES + nb * (16 * T_STRIDE) + ko);
                #pragma unroll
                for (int mb = 0; mb < 4; ++mb) {
                    MMA16816(acc[mb][2 * nb],     ah[mb], bh[0], bh[1]);
                    MMA16816(acc[mb][2 * nb],     ah[mb], bl[0], bl[1]);
                    MMA16816(acc[mb][2 * nb],     al[mb], bh[0], bh[1]);
                    MMA16816(acc[mb][2 * nb + 1], ah[mb], bh[2], bh[3]);
                    MMA16816(acc[mb][2 * nb + 1], ah[mb], bl[2], bl[3]);
                    MMA16816(acc[mb][2 * nb + 1], al[mb], bh[2], bh[3]);
                }
            }
        }
        __syncthreads();
        if (c + 2 < NC)
            issue_chunk(sb + (uint32_t)(c & 1) * BUF_BYTES, tid, (c + 2) * 32,
                        Ahi, Alo, lda, Whi, Wlo, ldw);
    }
}

// =======================================================================
// Stage 1: raw = x @ W1^T (M=32768, N=1024, K=512) -> a,b coefs + chunk P,Q
// grid (8, 256), 128 threads
// =======================================================================
__global__ __launch_bounds__(128, 2)
void hmma_stage1_kernel(const float* __restrict__ Avec,
                        const float* __restrict__ bias_h)
{
    extern __shared__ __align__(16) char smem[];
    const uint32_t sb = smem_u32(smem);

    float acc[4][8][4];
    #pragma unroll
    for (int i = 0; i < 4; ++i)
        #pragma unroll
        for (int j = 0; j < 8; ++j)
            #pragma unroll
            for (int q = 0; q < 4; ++q) acc[i][j][q] = 0.f;

    const int row0 = blockIdx.y * 128;
    const int col0 = blockIdx.x * 128;

    hmma_mainloop<16>(sb,
                      g_A3hi + 512 + (size_t)row0 * 1024,
                      g_A3lo + 512 + (size_t)row0 * 1024, 1024,
                      g_W1hi + (size_t)col0 * 512,
                      g_W1lo + (size_t)col0 * 512, 512,
                      acc);

    // -------- epilogue: gate math in-lane (pair cols), smem restage --------
    const int tid = threadIdx.x, wid = tid >> 5, lane = tid & 31;
    const int wm = (wid >> 1) * 64, wn = (wid & 1) * 64;
    const int g = lane >> 2, tig = lane & 3;
    const int hbase = col0 >> 1;

    float* sA = (float*)smem;              // [128][65]
    float* sB = sA + 128 * 65;             // [128][65]

    #pragma unroll
    for (int mb = 0; mb < 4; ++mb) {
        #pragma unroll
        for (int j = 0; j < 8; ++j) {
            int h_loc = (wn + (j >> 1) * 16 + (j & 1) * 8 + 2 * tig) >> 1;
            int hg = hbase + h_loc;
            float Ah = Avec[hg], Bh = bias_h[hg];
            int m0 = wm + mb * 16 + g;

            float g0 = 1.0f / (1.0f + __expf(-acc[mb][j][0]));
            g0 = fminf(fmaxf(g0, 0.05f), 0.95f);
            sA[m0 * 65 + h_loc] = 1.0f - g0 * (1.0f - Ah);
            sB[m0 * 65 + h_loc] = g0 * (acc[mb][j][1] + Bh);

            float g1 = 1.0f / (1.0f + __expf(-acc[mb][j][2]));
            g1 = fminf(fmaxf(g1, 0.05f), 0.95f);
            sA[(m0 + 8) * 65 + h_loc] = 1.0f - g1 * (1.0f - Ah);
            sB[(m0 + 8) * 65 + h_loc] = g1 * (acc[mb][j][3] + Bh);
        }
    }
    __syncthreads();

    // coalesced global write of a,b (128 threads: 2 groups x 64 cols)
    const int hh = tid & 63, rg = tid >> 6;
    #pragma unroll
    for (int r = 0; r < 64; ++r) {
        int row = rg * 64 + r;
        size_t gb = (size_t)(row0 + row) * DIM + hbase + hh;
        g_a[gb] = sA[row * 65 + hh];
        g_b[gb] = sB[row * 65 + hh];
    }

    // chunk summaries from smem: P = prod(a), Q = local-scan final (h_in = 0)
    if (tid < 64) {
        float p = 1.0f, q = 0.0f;
        #pragma unroll 4
        for (int r = 0; r < 128; ++r) {
            float a  = sA[r * 65 + tid];
            float bb = sB[r * 65 + tid];
            q = fmaf(a, q, bb);
            p *= a;
        }
        size_t o = (size_t)blockIdx.y * DIM + hbase + tid;
        g_P[o] = p;
        g_Q[o] = q;
    }
}

// =======================================================================
// final scan: per-block carry prefix over chunk summaries, then exact fp32
// recurrence with carry-in, emitting bf16 hi/lo into A3 cols [0,512).
// grid 256 x 512.
// =======================================================================
__global__ __launch_bounds__(512) void scan_final_kernel()
{
    const int bc = blockIdx.x;
    const int b  = bc / NCHUNK;
    const int c  = bc % NCHUNK;
    const int h  = threadIdx.x;

    // carry-in: sequential combine of prior chunk summaries (loads are
    // address-independent -> batched by the compiler for MLP)
    float hin = 0.0f;
    const size_t sbase = (size_t)b * NCHUNK * DIM + h;
    #pragma unroll 8
    for (int cc = 0; cc < c; ++cc) {
        const size_t o = sbase + (size_t)cc * DIM;
        hin = fmaf(g_P[o], hin, g_Q[o]);
    }

    const size_t base = ((size_t)b * SEQLEN + (size_t)c * CHUNK) * DIM + h;
    float hcur = hin;
    #pragma unroll 4
    for (int t = 0; t < CHUNK; ++t) {
        const size_t off = base + (size_t)t * DIM;
        hcur = fmaf(g_a[off], hcur, g_b[off]);
        __nv_bfloat16 hi, lo; bsplit(hcur, hi, lo);
        const size_t m = (size_t)(b * SEQLEN + c * CHUNK + t);
        g_A3hi[m * 1024 + h] = hi;
        g_A3lo[m * 1024 + h] = lo;
    }
}

// =======================================================================
// Stage 3: y = (hs@C^T + x@D^T + bias_y)*scale, K=1024 fused GEMM
// grid (4, 256), 128 threads
// =======================================================================
__global__ __launch_bounds__(128, 2)
void hmma_stage3_kernel(const float* __restrict__ bias_y, float* __restrict__ out)
{
    extern __shared__ __align__(16) char smem[];
    const uint32_t sb = smem_u32(smem);

    float acc[4][8][4];
    #pragma unroll
    for (int i = 0; i < 4; ++i)
        #pragma unroll
        for (int j = 0; j < 8; ++j)
            #pragma unroll
            for (int q = 0; q < 4; ++q) acc[i][j][q] = 0.f;

    const int row0 = blockIdx.y * 128;
    const int col0 = blockIdx.x * 128;

    hmma_mainloop<32>(sb,
                      g_A3hi + (size_t)row0 * 1024,
                      g_A3lo + (size_t)row0 * 1024, 1024,
                      g_W3hi + (size_t)col0 * 1024,
                      g_W3lo + (size_t)col0 * 1024, 1024,
                      acc);

    const int tid = threadIdx.x, wid = tid >> 5, lane = tid & 31;
    const int wm = (wid >> 1) * 64, wn = (wid & 1) * 64;
    const int g = lane >> 2, tig = lane & 3;
    const float scale = 0.04419417382415922f;   // 1/sqrt(512)

    float* sY = (float*)smem;                   // [128][129]

    #pragma unroll
    for (int mb = 0; mb < 4; ++mb) {
        #pragma unroll
        for (int j = 0; j < 8; ++j) {
            int n0 = wn + (j >> 1) * 16 + (j & 1) * 8 + 2 * tig;
            float by0 = bias_y[col0 + n0], by1 = bias_y[col0 + n0 + 1];
            int m0 = wm + mb * 16 + g;
            sY[m0 * 129 + n0]           = (acc[mb][j][0] + by0) * scale;
            sY[m0 * 129 + n0 + 1]       = (acc[mb][j][1] + by1) * scale;
            sY[(m0 + 8) * 129 + n0]     = (acc[mb][j][2] + by0) * scale;
            sY[(m0 + 8) * 129 + n0 + 1] = (acc[mb][j][3] + by1) * scale;
        }
    }
    __syncthreads();

    const int nn = tid;                         // 128 cols, 128 threads
    #pragma unroll 4
    for (int r = 0; r < 128; ++r)
        out[(size_t)(row0 + r) * DIM + col0 + nn] = sY[r * 129 + nn];
}

// =======================================================================
extern "C" void kernel_launch(void* const* d_in, const int* in_sizes, int n_in,
                              void* d_out, int out_size)
{
    const float* x      = (const float*)d_in[0];
    const float* Avec   = (const float*)d_in[1];
    const float* B      = (const float*)d_in[2];
    const float* C      = (const float*)d_in[3];
    const float* Dm     = (const float*)d_in[4];
    const float* Wg     = (const float*)d_in[5];
    const float* bias_h = (const float*)d_in[6];
    const float* bias_y = (const float*)d_in[7];
    float* out = (float*)d_out;

    cudaFuncSetAttribute(hmma_stage1_kernel,
                         cudaFuncAttributeMaxDynamicSharedMemorySize, SMEM_REQ);
    cudaFuncSetAttribute(hmma_stage3_kernel,
                         cudaFuncAttributeMaxDynamicSharedMemorySize, SMEM_REQ);

    conv_w_kernel<<<(1024 * 512 + 512 * 1024) / 256, 256>>>(Wg, B, C, Dm);
    conv_x_kernel<<<(MROWS * (DIM / 4)) / 256, 256>>>(x);

    hmma_stage1_kernel<<<dim3(8, MROWS / 128), 128, SMEM_REQ>>>(Avec, bias_h);

    scan_final_kernel<<<BATCH * NCHUNK, 512>>>();

    hmma_stage3_kernel<<<dim3(4, MROWS / 128), 128, SMEM_REQ>>>(bias_y, out);
}

// round 9
// speedup vs baseline: 1.5148x; 1.3405x over previous
#include <cuda_runtime.h>
#include <cuda_fp16.h>
#include <math.h>
#include <stdint.h>

#define BATCH   8
#define SEQLEN  4096
#define DIM     512
#define MROWS   (BATCH * SEQLEN)   // 32768
#define CHUNK_S 64
#define NCHUNK_S (SEQLEN / CHUNK_S)  // 64

// ================= static scratch =================
__device__ float g_a [(size_t)MROWS * DIM];
__device__ float g_b [(size_t)MROWS * DIM];
__device__ float g_P [BATCH * NCHUNK_S * DIM];
__device__ float g_Q [BATCH * NCHUNK_S * DIM];

// fp16 operands. A3 = [hs | x] : 32768 x 1024 (single fp16)
__device__ __align__(16) __half g_A3  [(size_t)MROWS * 1024];
// weights: 2-term fp16 split
__device__ __align__(16) __half g_W1hi[1024 * 512];   // interleaved [Wg;B]
__device__ __align__(16) __half g_W1lo[1024 * 512];
__device__ __align__(16) __half g_W3hi[512 * 1024];   // [C | D]
__device__ __align__(16) __half g_W3lo[512 * 1024];

// ================= PTX helpers (sm_80+ family-safe) ========
__device__ __forceinline__ uint32_t smem_u32(const void* p) {
    uint32_t a;
    asm("{ .reg .u64 t; cvta.to.shared.u64 t, %1; cvt.u32.u64 %0, t; }"
        : "=r"(a) : "l"(p));
    return a;
}
__device__ __forceinline__ void cp16(uint32_t s, const void* g) {
    asm volatile("cp.async.cg.shared.global [%0], [%1], 16;"
                 :: "r"(s), "l"(__cvta_generic_to_global(g)) : "memory");
}
#define CP_COMMIT() asm volatile("cp.async.commit_group;" ::: "memory")
#define CP_WAIT(n)  asm volatile("cp.async.wait_group %0;" :: "n"(n) : "memory")

#define LDSM4(r0, r1, r2, r3, addr) \
    asm volatile("ldmatrix.sync.aligned.m8n8.x4.shared.b16 {%0,%1,%2,%3}, [%4];" \
                 : "=r"(r0), "=r"(r1), "=r"(r2), "=r"(r3) : "r"(addr))

#define MMAH(c, a, b0, b1) \
    asm volatile("mma.sync.aligned.m16n8k16.row.col.f32.f16.f16.f32 " \
                 "{%0,%1,%2,%3}, {%4,%5,%6,%7}, {%8,%9}, {%0,%1,%2,%3};" \
                 : "+f"((c)[0]), "+f"((c)[1]), "+f"((c)[2]), "+f"((c)[3]) \
                 : "r"((a)[0]), "r"((a)[1]), "r"((a)[2]), "r"((a)[3]), \
                   "r"(b0), "r"(b1))

// smem tile: 128 rows x 32 fp16 (64B data), row stride 80B (ldmatrix conflict-free)
#define T_STRIDE 80
#define T_BYTES  (128 * T_STRIDE)          // 10240
#define BUF_BYTES (3 * T_BYTES)            // A, Whi, Wlo = 30720
#define SMEM_REQ  66560                    // max(2*BUF=61440, stage1 epilogue 66560)

// ================= fp16 split =================
__device__ __forceinline__ void hsplit(float v, __half& hi, __half& lo) {
    hi = __float2half_rn(v);
    lo = __float2half_rn(v - __half2float(hi));
}

// =======================================================================
// conv kernels
// =======================================================================
__global__ void conv_w_kernel(const float* __restrict__ Wg, const float* __restrict__ B,
                              const float* __restrict__ C,  const float* __restrict__ D)
{
    int idx = blockIdx.x * blockDim.x + threadIdx.x;
    if (idx < 1024 * 512) {
        int r = idx >> 9, k = idx & 511, h = r >> 1;
        float v = (r & 1) ? B[h * 512 + k] : Wg[h * 512 + k];
        __half hi, lo; hsplit(v, hi, lo);
        g_W1hi[idx] = hi; g_W1lo[idx] = lo;
    } else {
        int j = idx - 1024 * 512;
        int n = j >> 10, k = j & 1023;
        float v = (k < 512) ? C[n * 512 + k] : D[n * 512 + k - 512];
        __half hi, lo; hsplit(v, hi, lo);
        g_W3hi[j] = hi; g_W3lo[j] = lo;
    }
}

__global__ void conv_x_kernel(const float* __restrict__ x)
{
    size_t idx = (size_t)blockIdx.x * blockDim.x + threadIdx.x;   // float4 idx
    int cv = (int)(idx & 127);
    int m  = (int)(idx >> 7);
    float4 v = *(const float4*)&x[(size_t)m * 512 + cv * 4];
    __half2 p0 = __floats2half2_rn(v.x, v.y);
    __half2 p1 = __floats2half2_rn(v.z, v.w);
    size_t o = (size_t)m * 1024 + 512 + cv * 4;
    *(__half2*)&g_A3[o]     = p0;
    *(__half2*)&g_A3[o + 2] = p1;
}

// =======================================================================
// HMMA mainloop: CTA 128x128, 4 warps, warp tile 64x64, 2-stage cp.async
// A single fp16, W split hi/lo -> 2 MMAs per fragment pair
// =======================================================================
__device__ __forceinline__ void issue_chunk(
    uint32_t tb, int tid, int k0,
    const __half* __restrict__ A, int lda,
    const __half* __restrict__ Whi, const __half* __restrict__ Wlo, int ldw)
{
    #pragma unroll
    for (int i = 0; i < 4; ++i) {
        int v = i * 128 + tid;              // 0..511
        int r = v >> 2, ch = v & 3;
        uint32_t so = (uint32_t)(r * T_STRIDE + ch * 16);
        int go = k0 + ch * 8;
        cp16(tb +               so, A   + (size_t)r * lda + go);
        cp16(tb +     T_BYTES + so, Whi + (size_t)r * ldw + go);
        cp16(tb + 2 * T_BYTES + so, Wlo + (size_t)r * ldw + go);
    }
    CP_COMMIT();
}

template<int NC>
__device__ __forceinline__ void hmma_mainloop(
    uint32_t sb,
    const __half* __restrict__ A, int lda,
    const __half* __restrict__ Whi, const __half* __restrict__ Wlo, int ldw,
    float acc[4][8][4])
{
    const int tid  = threadIdx.x;
    const int wid  = tid >> 5, lane = tid & 31;
    const int wm   = (wid >> 1) * 64;       // warp m offset: 0 or 64
    const int wn   = (wid & 1) * 64;        // warp n offset: 0 or 64
    const uint32_t aSel = (uint32_t)((lane & 15) * T_STRIDE + (lane >> 4) * 16);
    const uint32_t bSel = (uint32_t)((((lane >> 4) << 3) + (lane & 7)) * T_STRIDE
                                     + ((lane >> 3) & 1) * 16);

    issue_chunk(sb,             tid, 0,  A, lda, Whi, Wlo, ldw);
    issue_chunk(sb + BUF_BYTES, tid, 32, A, lda, Whi, Wlo, ldw);

    #pragma unroll 1
    for (int c = 0; c < NC; ++c) {
        if (c + 1 == NC) { CP_WAIT(0); } else { CP_WAIT(1); }
        __syncthreads();

        const uint32_t tb = sb + (uint32_t)(c & 1) * BUF_BYTES;
        const uint32_t At = tb + (uint32_t)wm * T_STRIDE + aSel;
        const uint32_t Wh = tb +     T_BYTES + (uint32_t)wn * T_STRIDE + bSel;
        const uint32_t Wl = tb + 2 * T_BYTES + (uint32_t)wn * T_STRIDE + bSel;

        #pragma unroll
        for (int kk = 0; kk < 2; ++kk) {
            const uint32_t ko = kk * 32;    // 16 fp16 = 32B per k16 step
            uint32_t ah[4][4];
            #pragma unroll
            for (int mb = 0; mb < 4; ++mb)
                LDSM4(ah[mb][0], ah[mb][1], ah[mb][2], ah[mb][3],
                      At + mb * (16 * T_STRIDE) + ko);
            #pragma unroll
            for (int nb = 0; nb < 4; ++nb) {
                uint32_t wh[4], wl[4];
                LDSM4(wh[0], wh[1], wh[2], wh[3], Wh + nb * (16 * T_STRIDE) + ko);
                LDSM4(wl[0], wl[1], wl[2], wl[3], Wl + nb * (16 * T_STRIDE) + ko);
                #pragma unroll
                for (int mb = 0; mb < 4; ++mb) {
                    MMAH(acc[mb][2 * nb],     ah[mb], wh[0], wh[1]);
                    MMAH(acc[mb][2 * nb],     ah[mb], wl[0], wl[1]);
                    MMAH(acc[mb][2 * nb + 1], ah[mb], wh[2], wh[3]);
                    MMAH(acc[mb][2 * nb + 1], ah[mb], wl[2], wl[3]);
                }
            }
        }
        __syncthreads();
        if (c + 2 < NC)
            issue_chunk(sb + (uint32_t)(c & 1) * BUF_BYTES, tid, (c + 2) * 32,
                        A, lda, Whi, Wlo, ldw);
    }
}

// =======================================================================
// Stage 1: raw = x @ W1^T (M=32768, N=1024, K=512) -> a,b coefs + 64-row P,Q
// grid (8, 256), 128 threads
// =======================================================================
__global__ __launch_bounds__(128, 2)
void hmma_stage1_kernel(const float* __restrict__ Avec,
                        const float* __restrict__ bias_h)
{
    extern __shared__ __align__(16) char smem[];
    const uint32_t sb = smem_u32(smem);

    float acc[4][8][4];
    #pragma unroll
    for (int i = 0; i < 4; ++i)
        #pragma unroll
        for (int j = 0; j < 8; ++j)
            #pragma unroll
            for (int q = 0; q < 4; ++q) acc[i][j][q] = 0.f;

    const int row0 = blockIdx.y * 128;
    const int col0 = blockIdx.x * 128;

    hmma_mainloop<16>(sb,
                      g_A3 + 512 + (size_t)row0 * 1024, 1024,
                      g_W1hi + (size_t)col0 * 512,
                      g_W1lo + (size_t)col0 * 512, 512,
                      acc);

    // -------- epilogue: gate math in-lane (pair cols), smem restage --------
    const int tid = threadIdx.x, wid = tid >> 5, lane = tid & 31;
    const int wm = (wid >> 1) * 64, wn = (wid & 1) * 64;
    const int g = lane >> 2, tig = lane & 3;
    const int hbase = col0 >> 1;

    float* sA = (float*)smem;              // [128][65]
    float* sB = sA + 128 * 65;             // [128][65]

    #pragma unroll
    for (int mb = 0; mb < 4; ++mb) {
        #pragma unroll
        for (int j = 0; j < 8; ++j) {
            int h_loc = (wn + (j >> 1) * 16 + (j & 1) * 8 + 2 * tig) >> 1;
            int hg = hbase + h_loc;
            float Ah = Avec[hg], Bh = bias_h[hg];
            int m0 = wm + mb * 16 + g;

            float g0 = 1.0f / (1.0f + __expf(-acc[mb][j][0]));
            g0 = fminf(fmaxf(g0, 0.05f), 0.95f);
            sA[m0 * 65 + h_loc] = 1.0f - g0 * (1.0f - Ah);
            sB[m0 * 65 + h_loc] = g0 * (acc[mb][j][1] + Bh);

            float g1 = 1.0f / (1.0f + __expf(-acc[mb][j][2]));
            g1 = fminf(fmaxf(g1, 0.05f), 0.95f);
            sA[(m0 + 8) * 65 + h_loc] = 1.0f - g1 * (1.0f - Ah);
            sB[(m0 + 8) * 65 + h_loc] = g1 * (acc[mb][j][3] + Bh);
        }
    }
    __syncthreads();

    // coalesced global write of a,b (128 threads: 2 groups x 64 cols)
    const int hh = tid & 63, rg = tid >> 6;
    #pragma unroll
    for (int r = 0; r < 64; ++r) {
        int row = rg * 64 + r;
        size_t gb = (size_t)(row0 + row) * DIM + hbase + hh;
        g_a[gb] = sA[row * 65 + hh];
        g_b[gb] = sB[row * 65 + hh];
    }

    // sub-chunk summaries (64 rows each): P = prod(a), Q = local final (h_in=0)
    {
        const int sc = tid >> 6;           // 0..1
        const int hl = tid & 63;
        float p = 1.0f, q = 0.0f;
        #pragma unroll 4
        for (int r = sc * 64; r < sc * 64 + 64; ++r) {
            float a  = sA[r * 65 + hl];
            float bb = sB[r * 65 + hl];
            q = fmaf(a, q, bb);
            p *= a;
        }
        size_t o = ((size_t)blockIdx.y * 2 + sc) * DIM + hbase + hl;
        g_P[o] = p;
        g_Q[o] = q;
    }
}

// =======================================================================
// final scan: per-block carry prefix over sub-chunk summaries, then exact
// fp32 recurrence, emitting single fp16 into A3 cols [0,512).
// grid 512 x 512.
// =======================================================================
__global__ __launch_bounds__(512) void scan_final_kernel()
{
    const int bc = blockIdx.x;            // b*64 + cs
    const int b  = bc >> 6;
    const int cs = bc & 63;
    const int h  = threadIdx.x;

    float hin = 0.0f;
    const size_t sbase = ((size_t)b * NCHUNK_S) * DIM + h;
    #pragma unroll 8
    for (int cc = 0; cc < cs; ++cc) {
        const size_t o = sbase + (size_t)cc * DIM;
        hin = fmaf(g_P[o], hin, g_Q[o]);
    }

    const size_t base = ((size_t)b * SEQLEN + (size_t)cs * CHUNK_S) * DIM + h;
    float hcur = hin;
    #pragma unroll 4
    for (int t = 0; t < CHUNK_S; ++t) {
        const size_t off = base + (size_t)t * DIM;
        hcur = fmaf(g_a[off], hcur, g_b[off]);
        const size_t m = (size_t)(b * SEQLEN + cs * CHUNK_S + t);
        g_A3[m * 1024 + h] = __float2half_rn(hcur);
    }
}

// =======================================================================
// Stage 3: y = (hs@C^T + x@D^T + bias_y)*scale, K=1024 fused GEMM
// grid (4, 256), 128 threads
// =======================================================================
__global__ __launch_bounds__(128, 2)
void hmma_stage3_kernel(const float* __restrict__ bias_y, float* __restrict__ out)
{
    extern __shared__ __align__(16) char smem[];
    const uint32_t sb = smem_u32(smem);

    float acc[4][8][4];
    #pragma unroll
    for (int i = 0; i < 4; ++i)
        #pragma unroll
        for (int j = 0; j < 8; ++j)
            #pragma unroll
            for (int q = 0; q < 4; ++q) acc[i][j][q] = 0.f;

    const int row0 = blockIdx.y * 128;
    const int col0 = blockIdx.x * 128;

    hmma_mainloop<32>(sb,
                      g_A3 + (size_t)row0 * 1024, 1024,
                      g_W3hi + (size_t)col0 * 1024,
                      g_W3lo + (size_t)col0 * 1024, 1024,
                      acc);

    const int tid = threadIdx.x, wid = tid >> 5, lane = tid & 31;
    const int wm = (wid >> 1) * 64, wn = (wid & 1) * 64;
    const int g = lane >> 2, tig = lane & 3;
    const float scale = 0.04419417382415922f;   // 1/sqrt(512)

    float* sY = (float*)smem;                   // [128][129]

    #pragma unroll
    for (int mb = 0; mb < 4; ++mb) {
        #pragma unroll
        for (int j = 0; j < 8; ++j) {
            int n0 = wn + (j >> 1) * 16 + (j & 1) * 8 + 2 * tig;
            float by0 = bias_y[col0 + n0], by1 = bias_y[col0 + n0 + 1];
            int m0 = wm + mb * 16 + g;
            sY[m0 * 129 + n0]           = (acc[mb][j][0] + by0) * scale;
            sY[m0 * 129 + n0 + 1]       = (acc[mb][j][1] + by1) * scale;
            sY[(m0 + 8) * 129 + n0]     = (acc[mb][j][2] + by0) * scale;
            sY[(m0 + 8) * 129 + n0 + 1] = (acc[mb][j][3] + by1) * scale;
        }
    }
    __syncthreads();

    const int nn = tid;                         // 128 cols, 128 threads
    #pragma unroll 4
    for (int r = 0; r < 128; ++r)
        out[(size_t)(row0 + r) * DIM + col0 + nn] = sY[r * 129 + nn];
}

// =======================================================================
extern "C" void kernel_launch(void* const* d_in, const int* in_sizes, int n_in,
                              void* d_out, int out_size)
{
    const float* x      = (const float*)d_in[0];
    const float* Avec   = (const float*)d_in[1];
    const float* B      = (const float*)d_in[2];
    const float* C      = (const float*)d_in[3];
    const float* Dm     = (const float*)d_in[4];
    const float* Wg     = (const float*)d_in[5];
    const float* bias_h = (const float*)d_in[6];
    const float* bias_y = (const float*)d_in[7];
    float* out = (float*)d_out;

    cudaFuncSetAttribute(hmma_stage1_kernel,
                         cudaFuncAttributeMaxDynamicSharedMemorySize, SMEM_REQ);
    cudaFuncSetAttribute(hmma_stage3_kernel,
                         cudaFuncAttributeMaxDynamicSharedMemorySize, SMEM_REQ);

    conv_w_kernel<<<(1024 * 512 + 512 * 1024) / 256, 256>>>(Wg, B, C, Dm);
    conv_x_kernel<<<(MROWS * (DIM / 4)) / 256, 256>>>(x);

    hmma_stage1_kernel<<<dim3(8, MROWS / 128), 128, SMEM_REQ>>>(Avec, bias_h);

    scan_final_kernel<<<BATCH * NCHUNK_S, 512>>>();

    hmma_stage3_kernel<<<dim3(4, MROWS / 128), 128, SMEM_REQ>>>(bias_y, out);
}

// round 10
// speedup vs baseline: 1.8903x; 1.2479x over previous
#include <cuda_runtime.h>
#include <cuda_fp16.h>
#include <math.h>
#include <stdint.h>

#define BATCH   8
#define SEQLEN  4096
#define DIM     512
#define MROWS   (BATCH * SEQLEN)   // 32768
#define CHUNK_S 64
#define NCHUNK_S (SEQLEN / CHUNK_S)  // 64

// ================= static scratch =================
// packed coefficients: x = 1-a (fp16), y = b (fp16)
__device__ __align__(16) __half2 g_ab[(size_t)MROWS * DIM];   // 64 MB
__device__ float g_P [BATCH * NCHUNK_S * DIM];
__device__ float g_Q [BATCH * NCHUNK_S * DIM];

// fp16 operands. A3 = [hs | x] : 32768 x 1024 (single fp16)
__device__ __align__(16) __half g_A3  [(size_t)MROWS * 1024];
// W1 2-term split (stage1 is precision-sensitive)
__device__ __align__(16) __half g_W1hi[1024 * 512];
__device__ __align__(16) __half g_W1lo[1024 * 512];
// W3 single fp16 (stage3 is linear in weights)
__device__ __align__(16) __half g_W3  [512 * 1024];

// ================= PTX helpers (sm_80+ family-safe) ========
__device__ __forceinline__ uint32_t smem_u32(const void* p) {
    uint32_t a;
    asm("{ .reg .u64 t; cvta.to.shared.u64 t, %1; cvt.u32.u64 %0, t; }"
        : "=r"(a) : "l"(p));
    return a;
}
__device__ __forceinline__ void cp16(uint32_t s, const void* g) {
    asm volatile("cp.async.cg.shared.global [%0], [%1], 16;"
                 :: "r"(s), "l"(__cvta_generic_to_global(g)) : "memory");
}
#define CP_COMMIT() asm volatile("cp.async.commit_group;" ::: "memory")
#define CP_WAIT(n)  asm volatile("cp.async.wait_group %0;" :: "n"(n) : "memory")

#define LDSM4(r0, r1, r2, r3, addr) \
    asm volatile("ldmatrix.sync.aligned.m8n8.x4.shared.b16 {%0,%1,%2,%3}, [%4];" \
                 : "=r"(r0), "=r"(r1), "=r"(r2), "=r"(r3) : "r"(addr))

#define MMAH(c, a, b0, b1) \
    asm volatile("mma.sync.aligned.m16n8k16.row.col.f32.f16.f16.f32 " \
                 "{%0,%1,%2,%3}, {%4,%5,%6,%7}, {%8,%9}, {%0,%1,%2,%3};" \
                 : "+f"((c)[0]), "+f"((c)[1]), "+f"((c)[2]), "+f"((c)[3]) \
                 : "r"((a)[0]), "r"((a)[1]), "r"((a)[2]), "r"((a)[3]), \
                   "r"(b0), "r"(b1))

// smem tile: 128 rows x 32 fp16 (64B data), row stride 80B (ldmatrix conflict-free)
#define T_STRIDE 80
#define T_BYTES  (128 * T_STRIDE)          // 10240
#define SMEM_REQ 66560                     // stage1 epilogue is the max user

// ================= fp16 split =================
__device__ __forceinline__ void hsplit(float v, __half& hi, __half& lo) {
    hi = __float2half_rn(v);
    lo = __float2half_rn(v - __half2float(hi));
}

// =======================================================================
// conv kernels
// =======================================================================
__global__ void conv_w_kernel(const float* __restrict__ Wg, const float* __restrict__ B,
                              const float* __restrict__ C,  const float* __restrict__ D)
{
    int idx = blockIdx.x * blockDim.x + threadIdx.x;
    if (idx < 1024 * 512) {
        int r = idx >> 9, k = idx & 511, h = r >> 1;
        float v = (r & 1) ? B[h * 512 + k] : Wg[h * 512 + k];
        __half hi, lo; hsplit(v, hi, lo);
        g_W1hi[idx] = hi; g_W1lo[idx] = lo;
    } else {
        int j = idx - 1024 * 512;
        int n = j >> 10, k = j & 1023;
        float v = (k < 512) ? C[n * 512 + k] : D[n * 512 + k - 512];
        g_W3[j] = __float2half_rn(v);
    }
}

__global__ void conv_x_kernel(const float* __restrict__ x)
{
    size_t idx = (size_t)blockIdx.x * blockDim.x + threadIdx.x;   // float4 idx
    int cv = (int)(idx & 127);
    int m  = (int)(idx >> 7);
    float4 v = *(const float4*)&x[(size_t)m * 512 + cv * 4];
    size_t o = (size_t)m * 1024 + 512 + cv * 4;
    *(__half2*)&g_A3[o]     = __floats2half2_rn(v.x, v.y);
    *(__half2*)&g_A3[o + 2] = __floats2half2_rn(v.z, v.w);
}

// =======================================================================
// HMMA mainloop: CTA 128x128, 4 warps, warp tile 64x64, 2-stage cp.async
// SPLIT=true: W has hi/lo terms (2 MMAs); false: single W (1 MMA)
// =======================================================================
template<bool SPLIT>
__device__ __forceinline__ void issue_chunk(
    uint32_t tb, int tid, int k0,
    const __half* __restrict__ A, int lda,
    const __half* __restrict__ Whi, const __half* __restrict__ Wlo, int ldw)
{
    #pragma unroll
    for (int i = 0; i < 4; ++i) {
        int v = i * 128 + tid;              // 0..511
        int r = v >> 2, ch = v & 3;
        uint32_t so = (uint32_t)(r * T_STRIDE + ch * 16);
        int go = k0 + ch * 8;
        cp16(tb +           so, A   + (size_t)r * lda + go);
        cp16(tb + T_BYTES + so, Whi + (size_t)r * ldw + go);
        if (SPLIT) cp16(tb + 2 * T_BYTES + so, Wlo + (size_t)r * ldw + go);
    }
    CP_COMMIT();
}

template<int NC, bool SPLIT>
__device__ __forceinline__ void hmma_mainloop(
    uint32_t sb,
    const __half* __restrict__ A, int lda,
    const __half* __restrict__ Whi, const __half* __restrict__ Wlo, int ldw,
    float acc[4][8][4])
{
    constexpr uint32_t BUFB = (SPLIT ? 3u : 2u) * T_BYTES;
    const int tid  = threadIdx.x;
    const int wid  = tid >> 5, lane = tid & 31;
    const int wm   = (wid >> 1) * 64;
    const int wn   = (wid & 1) * 64;
    const uint32_t aSel = (uint32_t)((lane & 15) * T_STRIDE + (lane >> 4) * 16);
    const uint32_t bSel = (uint32_t)((((lane >> 4) << 3) + (lane & 7)) * T_STRIDE
                                     + ((lane >> 3) & 1) * 16);

    issue_chunk<SPLIT>(sb,        tid, 0,  A, lda, Whi, Wlo, ldw);
    issue_chunk<SPLIT>(sb + BUFB, tid, 32, A, lda, Whi, Wlo, ldw);

    #pragma unroll 1
    for (int c = 0; c < NC; ++c) {
        if (c + 1 == NC) { CP_WAIT(0); } else { CP_WAIT(1); }
        __syncthreads();

        const uint32_t tb = sb + (uint32_t)(c & 1) * BUFB;
        const uint32_t At = tb + (uint32_t)wm * T_STRIDE + aSel;
        const uint32_t Wh = tb + T_BYTES + (uint32_t)wn * T_STRIDE + bSel;

        #pragma unroll
        for (int kk = 0; kk < 2; ++kk) {
            const uint32_t ko = kk * 32;    // 16 fp16 = 32B per k16 step
            uint32_t ah[4][4];
            #pragma unroll
            for (int mb = 0; mb < 4; ++mb)
                LDSM4(ah[mb][0], ah[mb][1], ah[mb][2], ah[mb][3],
                      At + mb * (16 * T_STRIDE) + ko);
            #pragma unroll
            for (int nb = 0; nb < 4; ++nb) {
                uint32_t wh[4];
                LDSM4(wh[0], wh[1], wh[2], wh[3], Wh + nb * (16 * T_STRIDE) + ko);
                #pragma unroll
                for (int mb = 0; mb < 4; ++mb) {
                    MMAH(acc[mb][2 * nb],     ah[mb], wh[0], wh[1]);
                    MMAH(acc[mb][2 * nb + 1], ah[mb], wh[2], wh[3]);
                }
                if (SPLIT) {
                    uint32_t wl[4];
                    LDSM4(wl[0], wl[1], wl[2], wl[3],
                          Wh + T_BYTES + nb * (16 * T_STRIDE) + ko);
                    #pragma unroll
                    for (int mb = 0; mb < 4; ++mb) {
                        MMAH(acc[mb][2 * nb],     ah[mb], wl[0], wl[1]);
                        MMAH(acc[mb][2 * nb + 1], ah[mb], wl[2], wl[3]);
                    }
                }
            }
        }
        __syncthreads();
        if (c + 2 < NC)
            issue_chunk<SPLIT>(sb + (uint32_t)(c & 1) * BUFB, tid, (c + 2) * 32,
                               A, lda, Whi, Wlo, ldw);
    }
}

// =======================================================================
// Stage 1: raw = x @ W1^T (M=32768, N=1024, K=512) -> (1-a, b) fp16 + P,Q
// grid (8, 256), 128 threads
// =======================================================================
__global__ __launch_bounds__(128, 2)
void hmma_stage1_kernel(const float* __restrict__ Avec,
                        const float* __restrict__ bias_h)
{
    extern __shared__ __align__(16) char smem[];
    const uint32_t sb = smem_u32(smem);

    float acc[4][8][4];
    #pragma unroll
    for (int i = 0; i < 4; ++i)
        #pragma unroll
        for (int j = 0; j < 8; ++j)
            #pragma unroll
            for (int q = 0; q < 4; ++q) acc[i][j][q] = 0.f;

    const int row0 = blockIdx.y * 128;
    const int col0 = blockIdx.x * 128;

    hmma_mainloop<16, true>(sb,
                            g_A3 + 512 + (size_t)row0 * 1024, 1024,
                            g_W1hi + (size_t)col0 * 512,
                            g_W1lo + (size_t)col0 * 512, 512,
                            acc);

    // -------- epilogue: gate math, quantize (1-a, b) to fp16, restage ------
    const int tid = threadIdx.x, wid = tid >> 5, lane = tid & 31;
    const int wm = (wid >> 1) * 64, wn = (wid & 1) * 64;
    const int g = lane >> 2, tig = lane & 3;
    const int hbase = col0 >> 1;

    float* sA = (float*)smem;              // [128][65]  quantized (1-a)
    float* sB = sA + 128 * 65;             // [128][65]  quantized b

    #pragma unroll
    for (int mb = 0; mb < 4; ++mb) {
        #pragma unroll
        for (int j = 0; j < 8; ++j) {
            int h_loc = (wn + (j >> 1) * 16 + (j & 1) * 8 + 2 * tig) >> 1;
            int hg = hbase + h_loc;
            float Ah = Avec[hg], Bh = bias_h[hg];
            int m0 = wm + mb * 16 + g;

            float g0 = 1.0f / (1.0f + __expf(-acc[mb][j][0]));
            g0 = fminf(fmaxf(g0, 0.05f), 0.95f);
            sA[m0 * 65 + h_loc] = __half2float(__float2half_rn(g0 * (1.0f - Ah)));
            sB[m0 * 65 + h_loc] = __half2float(__float2half_rn(g0 * (acc[mb][j][1] + Bh)));

            float g1 = 1.0f / (1.0f + __expf(-acc[mb][j][2]));
            g1 = fminf(fmaxf(g1, 0.05f), 0.95f);
            sA[(m0 + 8) * 65 + h_loc] = __half2float(__float2half_rn(g1 * (1.0f - Ah)));
            sB[(m0 + 8) * 65 + h_loc] = __half2float(__float2half_rn(g1 * (acc[mb][j][3] + Bh)));
        }
    }
    __syncthreads();

    // coalesced packed write (values already half-representable -> exact)
    const int hh = tid & 63, rg = tid >> 6;
    #pragma unroll
    for (int r = 0; r < 64; ++r) {
        int row = rg * 64 + r;
        size_t gb = (size_t)(row0 + row) * DIM + hbase + hh;
        g_ab[gb] = __floats2half2_rn(sA[row * 65 + hh], sB[row * 65 + hh]);
    }

    // sub-chunk summaries (64 rows): P = prod(a), Q = local final (h_in=0),
    // computed from the QUANTIZED coefficients for exact carry consistency.
    {
        const int sc = tid >> 6;           // 0..1
        const int hl = tid & 63;
        float p = 1.0f, q = 0.0f;
        #pragma unroll 4
        for (int r = sc * 64; r < sc * 64 + 64; ++r) {
            float a  = 1.0f - sA[r * 65 + hl];
            float bb = sB[r * 65 + hl];
            q = fmaf(a, q, bb);
            p *= a;
        }
        size_t o = ((size_t)blockIdx.y * 2 + sc) * DIM + hbase + hl;
        g_P[o] = p;
        g_Q[o] = q;
    }
}

// =======================================================================
// final scan: carry prefix over sub-chunk summaries, exact fp32 recurrence
// on quantized coefficients, emit fp16 into A3 cols [0,512). grid 512x512.
// =======================================================================
__global__ __launch_bounds__(512) void scan_final_kernel()
{
    const int bc = blockIdx.x;            // b*64 + cs
    const int b  = bc >> 6;
    const int cs = bc & 63;
    const int h  = threadIdx.x;

    float hin = 0.0f;
    const size_t sbase = ((size_t)b * NCHUNK_S) * DIM + h;
    #pragma unroll 8
    for (int cc = 0; cc < cs; ++cc) {
        const size_t o = sbase + (size_t)cc * DIM;
        hin = fmaf(g_P[o], hin, g_Q[o]);
    }

    const size_t base = ((size_t)b * SEQLEN + (size_t)cs * CHUNK_S) * DIM + h;
    float hcur = hin;
    #pragma unroll 4
    for (int t = 0; t < CHUNK_S; ++t) {
        __half2 ab = g_ab[base + (size_t)t * DIM];
        float a  = 1.0f - __half2float(__low2half(ab));
        float bb = __half2float(__high2half(ab));
        hcur = fmaf(a, hcur, bb);
        const size_t m = (size_t)(b * SEQLEN + cs * CHUNK_S + t);
        g_A3[m * 1024 + h] = __float2half_rn(hcur);
    }
}

// =======================================================================
// Stage 3: y = (hs@C^T + x@D^T + bias_y)*scale, K=1024, single-fp16 W
// grid (4, 256), 128 threads
// =======================================================================
__global__ __launch_bounds__(128, 2)
void hmma_stage3_kernel(const float* __restrict__ bias_y, float* __restrict__ out)
{
    extern __shared__ __align__(16) char smem[];
    const uint32_t sb = smem_u32(smem);

    float acc[4][8][4];
    #pragma unroll
    for (int i = 0; i < 4; ++i)
        #pragma unroll
        for (int j = 0; j < 8; ++j)
            #pragma unroll
            for (int q = 0; q < 4; ++q) acc[i][j][q] = 0.f;

    const int row0 = blockIdx.y * 128;
    const int col0 = blockIdx.x * 128;

    hmma_mainloop<32, false>(sb,
                             g_A3 + (size_t)row0 * 1024, 1024,
                             g_W3 + (size_t)col0 * 1024, (const __half*)0, 1024,
                             acc);

    const int tid = threadIdx.x, wid = tid >> 5, lane = tid & 31;
    const int wm = (wid >> 1) * 64, wn = (wid & 1) * 64;
    const int g = lane >> 2, tig = lane & 3;
    const float scale = 0.04419417382415922f;   // 1/sqrt(512)

    float* sY = (float*)smem;                   // [128][129]

    #pragma unroll
    for (int mb = 0; mb < 4; ++mb) {
        #pragma unroll
        for (int j = 0; j < 8; ++j) {
            int n0 = wn + (j >> 1) * 16 + (j & 1) * 8 + 2 * tig;
            float by0 = bias_y[col0 + n0], by1 = bias_y[col0 + n0 + 1];
            int m0 = wm + mb * 16 + g;
            sY[m0 * 129 + n0]           = (acc[mb][j][0] + by0) * scale;
            sY[m0 * 129 + n0 + 1]       = (acc[mb][j][1] + by1) * scale;
            sY[(m0 + 8) * 129 + n0]     = (acc[mb][j][2] + by0) * scale;
            sY[(m0 + 8) * 129 + n0 + 1] = (acc[mb][j][3] + by1) * scale;
        }
    }
    __syncthreads();

    const int nn = tid;                         // 128 cols, 128 threads
    #pragma unroll 4
    for (int r = 0; r < 128; ++r)
        out[(size_t)(row0 + r) * DIM + col0 + nn] = sY[r * 129 + nn];
}

// =======================================================================
extern "C" void kernel_launch(void* const* d_in, const int* in_sizes, int n_in,
                              void* d_out, int out_size)
{
    const float* x      = (const float*)d_in[0];
    const float* Avec   = (const float*)d_in[1];
    const float* B      = (const float*)d_in[2];
    const float* C      = (const float*)d_in[3];
    const float* Dm     = (const float*)d_in[4];
    const float* Wg     = (const float*)d_in[5];
    const float* bias_h = (const float*)d_in[6];
    const float* bias_y = (const float*)d_in[7];
    float* out = (float*)d_out;

    cudaFuncSetAttribute(hmma_stage1_kernel,
                         cudaFuncAttributeMaxDynamicSharedMemorySize, SMEM_REQ);
    cudaFuncSetAttribute(hmma_stage3_kernel,
                         cudaFuncAttributeMaxDynamicSharedMemorySize, SMEM_REQ);

    conv_w_kernel<<<(1024 * 512 + 512 * 1024) / 256, 256>>>(Wg, B, C, Dm);
    conv_x_kernel<<<(MROWS * (DIM / 4)) / 256, 256>>>(x);

    hmma_stage1_kernel<<<dim3(8, MROWS / 128), 128, SMEM_REQ>>>(Avec, bias_h);

    scan_final_kernel<<<BATCH * NCHUNK_S, 512>>>();

    hmma_stage3_kernel<<<dim3(4, MROWS / 128), 128, SMEM_REQ>>>(bias_y, out);
}

// round 11
// speedup vs baseline: 2.3529x; 1.2447x over previous
#include <cuda_runtime.h>
#include <cuda_fp16.h>
#include <math.h>
#include <stdint.h>

#define BATCH   8
#define SEQLEN  4096
#define DIM     512
#define MROWS   (BATCH * SEQLEN)   // 32768
#define CHUNK_S 64
#define NCHUNK_S (SEQLEN / CHUNK_S)  // 64

// ================= static scratch =================
// packed coefficients: lo = 1-a (fp16), hi = b (fp16)
__device__ __align__(16) __half2 g_ab[(size_t)MROWS * DIM];   // 64 MB
__device__ float g_P [BATCH * NCHUNK_S * DIM];
__device__ float g_Q [BATCH * NCHUNK_S * DIM];

// fp16 operands. A3 = [hs | x] : 32768 x 1024
__device__ __align__(16) __half g_A3[(size_t)MROWS * 1024];
__device__ __align__(16) __half g_W1[1024 * 512];    // interleaved [Wg;B]
__device__ __align__(16) __half g_W3[512 * 1024];    // [C | D]

// ================= PTX helpers (sm_80+ family-safe) ========
__device__ __forceinline__ uint32_t smem_u32(const void* p) {
    uint32_t a;
    asm("{ .reg .u64 t; cvta.to.shared.u64 t, %1; cvt.u32.u64 %0, t; }"
        : "=r"(a) : "l"(p));
    return a;
}
__device__ __forceinline__ void cp16(uint32_t s, const void* g) {
    asm volatile("cp.async.cg.shared.global [%0], [%1], 16;"
                 :: "r"(s), "l"(__cvta_generic_to_global(g)) : "memory");
}
#define CP_COMMIT() asm volatile("cp.async.commit_group;" ::: "memory")
#define CP_WAIT(n)  asm volatile("cp.async.wait_group %0;" :: "n"(n) : "memory")

#define LDSM4(r0, r1, r2, r3, addr) \
    asm volatile("ldmatrix.sync.aligned.m8n8.x4.shared.b16 {%0,%1,%2,%3}, [%4];" \
                 : "=r"(r0), "=r"(r1), "=r"(r2), "=r"(r3) : "r"(addr))

#define MMAH(c, a, b0, b1) \
    asm volatile("mma.sync.aligned.m16n8k16.row.col.f32.f16.f16.f32 " \
                 "{%0,%1,%2,%3}, {%4,%5,%6,%7}, {%8,%9}, {%0,%1,%2,%3};" \
                 : "+f"((c)[0]), "+f"((c)[1]), "+f"((c)[2]), "+f"((c)[3]) \
                 : "r"((a)[0]), "r"((a)[1]), "r"((a)[2]), "r"((a)[3]), \
                   "r"(b0), "r"(b1))

// smem tile: 128 rows x 32 fp16 (64B data), row stride 80B (ldmatrix conflict-free)
#define T_STRIDE 80
#define T_BYTES  (128 * T_STRIDE)          // 10240
#define BUF_BYTES (2 * T_BYTES)            // A + W = 20480
#define SMEM_REQ 66560                     // stage1 epilogue is the max user

// =======================================================================
// conv kernels
// =======================================================================
__global__ void conv_w_kernel(const float* __restrict__ Wg, const float* __restrict__ B,
                              const float* __restrict__ C,  const float* __restrict__ D)
{
    int idx = blockIdx.x * blockDim.x + threadIdx.x;
    if (idx < 1024 * 512) {
        int r = idx >> 9, k = idx & 511, h = r >> 1;
        float v = (r & 1) ? B[h * 512 + k] : Wg[h * 512 + k];
        g_W1[idx] = __float2half_rn(v);
    } else {
        int j = idx - 1024 * 512;
        int n = j >> 10, k = j & 1023;
        float v = (k < 512) ? C[n * 512 + k] : D[n * 512 + k - 512];
        g_W3[j] = __float2half_rn(v);
    }
}

__global__ void conv_x_kernel(const float* __restrict__ x)
{
    size_t idx = (size_t)blockIdx.x * blockDim.x + threadIdx.x;   // float4 idx
    int cv = (int)(idx & 127);
    int m  = (int)(idx >> 7);
    float4 v = *(const float4*)&x[(size_t)m * 512 + cv * 4];
    size_t o = (size_t)m * 1024 + 512 + cv * 4;
    *(__half2*)&g_A3[o]     = __floats2half2_rn(v.x, v.y);
    *(__half2*)&g_A3[o + 2] = __floats2half2_rn(v.z, v.w);
}

// =======================================================================
// HMMA mainloop: CTA 128x128, 4 warps, warp tile 64x64, 2-stage cp.async,
// single-fp16 operands (1 MMA per fragment pair)
// =======================================================================
__device__ __forceinline__ void issue_chunk(
    uint32_t tb, int tid, int k0,
    const __half* __restrict__ A, int lda,
    const __half* __restrict__ W, int ldw)
{
    #pragma unroll
    for (int i = 0; i < 4; ++i) {
        int v = i * 128 + tid;              // 0..511
        int r = v >> 2, ch = v & 3;
        uint32_t so = (uint32_t)(r * T_STRIDE + ch * 16);
        int go = k0 + ch * 8;
        cp16(tb +           so, A + (size_t)r * lda + go);
        cp16(tb + T_BYTES + so, W + (size_t)r * ldw + go);
    }
    CP_COMMIT();
}

template<int NC>
__device__ __forceinline__ void hmma_mainloop(
    uint32_t sb,
    const __half* __restrict__ A, int lda,
    const __half* __restrict__ W, int ldw,
    float acc[4][8][4])
{
    const int tid  = threadIdx.x;
    const int wid  = tid >> 5, lane = tid & 31;
    const int wm   = (wid >> 1) * 64;
    const int wn   = (wid & 1) * 64;
    const uint32_t aSel = (uint32_t)((lane & 15) * T_STRIDE + (lane >> 4) * 16);
    const uint32_t bSel = (uint32_t)((((lane >> 4) << 3) + (lane & 7)) * T_STRIDE
                                     + ((lane >> 3) & 1) * 16);

    issue_chunk(sb,             tid, 0,  A, lda, W, ldw);
    issue_chunk(sb + BUF_BYTES, tid, 32, A, lda, W, ldw);

    #pragma unroll 1
    for (int c = 0; c < NC; ++c) {
        if (c + 1 == NC) { CP_WAIT(0); } else { CP_WAIT(1); }
        __syncthreads();

        const uint32_t tb = sb + (uint32_t)(c & 1) * BUF_BYTES;
        const uint32_t At = tb + (uint32_t)wm * T_STRIDE + aSel;
        const uint32_t Wt = tb + T_BYTES + (uint32_t)wn * T_STRIDE + bSel;

        #pragma unroll
        for (int kk = 0; kk < 2; ++kk) {
            const uint32_t ko = kk * 32;    // 16 fp16 = 32B per k16 step
            uint32_t ah[4][4];
            #pragma unroll
            for (int mb = 0; mb < 4; ++mb)
                LDSM4(ah[mb][0], ah[mb][1], ah[mb][2], ah[mb][3],
                      At + mb * (16 * T_STRIDE) + ko);
            #pragma unroll
            for (int nb = 0; nb < 4; ++nb) {
                uint32_t wh[4];
                LDSM4(wh[0], wh[1], wh[2], wh[3], Wt + nb * (16 * T_STRIDE) + ko);
                #pragma unroll
                for (int mb = 0; mb < 4; ++mb) {
                    MMAH(acc[mb][2 * nb],     ah[mb], wh[0], wh[1]);
                    MMAH(acc[mb][2 * nb + 1], ah[mb], wh[2], wh[3]);
                }
            }
        }
        __syncthreads();
        if (c + 2 < NC)
            issue_chunk(sb + (uint32_t)(c & 1) * BUF_BYTES, tid, (c + 2) * 32,
                        A, lda, W, ldw);
    }
}

// =======================================================================
// Stage 1: raw = x @ W1^T (M=32768, N=1024, K=512) -> (1-a, b) fp16 + P,Q
// grid (8, 256), 128 threads
// =======================================================================
__global__ __launch_bounds__(128, 2)
void hmma_stage1_kernel(const float* __restrict__ Avec,
                        const float* __restrict__ bias_h)
{
    extern __shared__ __align__(16) char smem[];
    const uint32_t sb = smem_u32(smem);

    float acc[4][8][4];
    #pragma unroll
    for (int i = 0; i < 4; ++i)
        #pragma unroll
        for (int j = 0; j < 8; ++j)
            #pragma unroll
            for (int q = 0; q < 4; ++q) acc[i][j][q] = 0.f;

    const int row0 = blockIdx.y * 128;
    const int col0 = blockIdx.x * 128;

    hmma_mainloop<16>(sb,
                      g_A3 + 512 + (size_t)row0 * 1024, 1024,
                      g_W1 + (size_t)col0 * 512, 512,
                      acc);

    // -------- epilogue: gate math, quantize (1-a, b) to fp16, restage ------
    const int tid = threadIdx.x, wid = tid >> 5, lane = tid & 31;
    const int wm = (wid >> 1) * 64, wn = (wid & 1) * 64;
    const int g = lane >> 2, tig = lane & 3;
    const int hbase = col0 >> 1;

    float* sA = (float*)smem;              // [128][65]  quantized (1-a)
    float* sB = sA + 128 * 65;             // [128][65]  quantized b

    #pragma unroll
    for (int mb = 0; mb < 4; ++mb) {
        #pragma unroll
        for (int j = 0; j < 8; ++j) {
            int h_loc = (wn + (j >> 1) * 16 + (j & 1) * 8 + 2 * tig) >> 1;
            int hg = hbase + h_loc;
            float Ah = Avec[hg], Bh = bias_h[hg];
            int m0 = wm + mb * 16 + g;

            float g0 = 1.0f / (1.0f + __expf(-acc[mb][j][0]));
            g0 = fminf(fmaxf(g0, 0.05f), 0.95f);
            sA[m0 * 65 + h_loc] = __half2float(__float2half_rn(g0 * (1.0f - Ah)));
            sB[m0 * 65 + h_loc] = __half2float(__float2half_rn(g0 * (acc[mb][j][1] + Bh)));

            float g1 = 1.0f / (1.0f + __expf(-acc[mb][j][2]));
            g1 = fminf(fmaxf(g1, 0.05f), 0.95f);
            sA[(m0 + 8) * 65 + h_loc] = __half2float(__float2half_rn(g1 * (1.0f - Ah)));
            sB[(m0 + 8) * 65 + h_loc] = __half2float(__float2half_rn(g1 * (acc[mb][j][3] + Bh)));
        }
    }
    __syncthreads();

    // coalesced packed write (values already half-representable -> exact)
    const int hh = tid & 63, rg = tid >> 6;
    #pragma unroll
    for (int r = 0; r < 64; ++r) {
        int row = rg * 64 + r;
        size_t gb = (size_t)(row0 + row) * DIM + hbase + hh;
        g_ab[gb] = __floats2half2_rn(sA[row * 65 + hh], sB[row * 65 + hh]);
    }

    // sub-chunk summaries (64 rows): P = prod(a), Q = local final (h_in=0),
    // computed from the QUANTIZED coefficients for exact carry consistency.
    {
        const int sc = tid >> 6;           // 0..1
        const int hl = tid & 63;
        float p = 1.0f, q = 0.0f;
        #pragma unroll 4
        for (int r = sc * 64; r < sc * 64 + 64; ++r) {
            float a  = 1.0f - sA[r * 65 + hl];
            float bb = sB[r * 65 + hl];
            q = fmaf(a, q, bb);
            p *= a;
        }
        size_t o = ((size_t)blockIdx.y * 2 + sc) * DIM + hbase + hl;
        g_P[o] = p;
        g_Q[o] = q;
    }
}

// =======================================================================
// final scan: carry prefix over sub-chunk summaries, exact fp32 recurrence
// on quantized coefficients, emit fp16 into A3 cols [0,512). grid 512x512.
// =======================================================================
__global__ __launch_bounds__(512) void scan_final_kernel()
{
    const int bc = blockIdx.x;            // b*64 + cs
    const int b  = bc >> 6;
    const int cs = bc & 63;
    const int h  = threadIdx.x;

    float hin = 0.0f;
    const size_t sbase = ((size_t)b * NCHUNK_S) * DIM + h;
    #pragma unroll 8
    for (int cc = 0; cc < cs; ++cc) {
        const size_t o = sbase + (size_t)cc * DIM;
        hin = fmaf(g_P[o], hin, g_Q[o]);
    }

    const size_t base = ((size_t)b * SEQLEN + (size_t)cs * CHUNK_S) * DIM + h;
    float hcur = hin;
    #pragma unroll 4
    for (int t = 0; t < CHUNK_S; ++t) {
        __half2 ab = g_ab[base + (size_t)t * DIM];
        float a  = 1.0f - __half2float(__low2half(ab));
        float bb = __half2float(__high2half(ab));
        hcur = fmaf(a, hcur, bb);
        const size_t m = (size_t)(b * SEQLEN + cs * CHUNK_S + t);
        g_A3[m * 1024 + h] = __float2half_rn(hcur);
    }
}

// =======================================================================
// Stage 3: y = (hs@C^T + x@D^T + bias_y)*scale, K=1024, single-fp16 W
// grid (4, 256), 128 threads
// =======================================================================
__global__ __launch_bounds__(128, 2)
void hmma_stage3_kernel(const float* __restrict__ bias_y, float* __restrict__ out)
{
    extern __shared__ __align__(16) char smem[];
    const uint32_t sb = smem_u32(smem);

    float acc[4][8][4];
    #pragma unroll
    for (int i = 0; i < 4; ++i)
        #pragma unroll
        for (int j = 0; j < 8; ++j)
            #pragma unroll
            for (int q = 0; q < 4; ++q) acc[i][j][q] = 0.f;

    const int row0 = blockIdx.y * 128;
    const int col0 = blockIdx.x * 128;

    hmma_mainloop<32>(sb,
                      g_A3 + (size_t)row0 * 1024, 1024,
                      g_W3 + (size_t)col0 * 1024, 1024,
                      acc);

    const int tid = threadIdx.x, wid = tid >> 5, lane = tid & 31;
    const int wm = (wid >> 1) * 64, wn = (wid & 1) * 64;
    const int g = lane >> 2, tig = lane & 3;
    const float scale = 0.04419417382415922f;   // 1/sqrt(512)

    float* sY = (float*)smem;                   // [128][129]

    #pragma unroll
    for (int mb = 0; mb < 4; ++mb) {
        #pragma unroll
        for (int j = 0; j < 8; ++j) {
            int n0 = wn + (j >> 1) * 16 + (j & 1) * 8 + 2 * tig;
            float by0 = bias_y[col0 + n0], by1 = bias_y[col0 + n0 + 1];
            int m0 = wm + mb * 16 + g;
            sY[m0 * 129 + n0]           = (acc[mb][j][0] + by0) * scale;
            sY[m0 * 129 + n0 + 1]       = (acc[mb][j][1] + by1) * scale;
            sY[(m0 + 8) * 129 + n0]     = (acc[mb][j][2] + by0) * scale;
            sY[(m0 + 8) * 129 + n0 + 1] = (acc[mb][j][3] + by1) * scale;
        }
    }
    __syncthreads();

    const int nn = tid;                         // 128 cols, 128 threads
    #pragma unroll 4
    for (int r = 0; r < 128; ++r)
        out[(size_t)(row0 + r) * DIM + col0 + nn] = sY[r * 129 + nn];
}

// =======================================================================
extern "C" void kernel_launch(void* const* d_in, const int* in_sizes, int n_in,
                              void* d_out, int out_size)
{
    const float* x      = (const float*)d_in[0];
    const float* Avec   = (const float*)d_in[1];
    const float* B      = (const float*)d_in[2];
    const float* C      = (const float*)d_in[3];
    const float* Dm     = (const float*)d_in[4];
    const float* Wg     = (const float*)d_in[5];
    const float* bias_h = (const float*)d_in[6];
    const float* bias_y = (const float*)d_in[7];
    float* out = (float*)d_out;

    cudaFuncSetAttribute(hmma_stage1_kernel,
                         cudaFuncAttributeMaxDynamicSharedMemorySize, SMEM_REQ);
    cudaFuncSetAttribute(hmma_stage3_kernel,
                         cudaFuncAttributeMaxDynamicSharedMemorySize, SMEM_REQ);

    conv_w_kernel<<<(1024 * 512 + 512 * 1024) / 256, 256>>>(Wg, B, C, Dm);
    conv_x_kernel<<<(MROWS * (DIM / 4)) / 256, 256>>>(x);

    hmma_stage1_kernel<<<dim3(8, MROWS / 128), 128, SMEM_REQ>>>(Avec, bias_h);

    scan_final_kernel<<<BATCH * NCHUNK_S, 512>>>();

    hmma_stage3_kernel<<<dim3(4, MROWS / 128), 128, SMEM_REQ>>>(bias_y, out);
}